// round 12
// baseline (speedup 1.0000x reference)
#include <cuda_runtime.h>
#include <cstddef>
#include <cstdint>

// ---------------------------------------------------------------------------
// Problem constants
// ---------------------------------------------------------------------------
#define N_NODES 50000
#define F_IN    768
#define PROJ    1024
#define HID     256
#define OUT_D   128
#define MAXE    500000

// ---------------------------------------------------------------------------
// Static device scratch
// ---------------------------------------------------------------------------
__device__ float g_A1 [(size_t)N_NODES * HID];
__device__ float g_A2 [(size_t)N_NODES * HID];
__device__ float g_C1 [(size_t)N_NODES * HID];
__device__ float g_CR3[(size_t)N_NODES * HID];
__device__ float g_h1 [(size_t)N_NODES * HID];
__device__ float g_M2 [(size_t)N_NODES * HID];
__device__ float g_h2 [(size_t)N_NODES * HID];
__device__ float g_g2 [(size_t)N_NODES * HID];
__device__ float g_h3 [(size_t)N_NODES * HID];
__device__ float g_Wfa  [(size_t)F_IN * 512];   // [W1@Wl1 | W1@Wl2]
__device__ float g_Wcc  [(size_t)F_IN * 256];   // W2@Wr1
__device__ float g_Wfa_t[(size_t)512 * F_IN];   // transposed, tf32-rounded
__device__ float g_Wcc_t[(size_t)512 * F_IN];   // rows 0-255: (W2@Wr1)^T, 256-511: Wr3^T
__device__ float g_Wr2_t[(size_t)HID * HID];
__device__ float g_Wl3_t[(size_t)HID * HID];
__device__ float g_W3_t [(size_t)OUT_D * HID];
__device__ float g_bfa[512];
__device__ float g_bcc[512];
__device__ int g_rp0[N_NODES + 1], g_rp1[N_NODES + 1], g_rp2[N_NODES + 1];
__device__ int g_cnt[3 * N_NODES];              // histogram then fill cursor, 3 graphs
__device__ int g_col0[MAXE], g_col1[MAXE], g_col2[MAXE];

// ---------------------------------------------------------------------------
// tf32 helpers
// ---------------------------------------------------------------------------
__device__ __forceinline__ uint32_t f2tf32(float f) {
    uint32_t u;
    asm("cvt.rna.tf32.f32 %0, %1;" : "=r"(u) : "f"(f));
    return u;
}

__device__ __forceinline__ void mma_tf32(float* c, const uint32_t* a, const uint32_t* b) {
    asm volatile(
        "mma.sync.aligned.m16n8k8.row.col.f32.tf32.tf32.f32 "
        "{%0,%1,%2,%3}, {%4,%5,%6,%7}, {%8,%9}, {%0,%1,%2,%3};"
        : "+f"(c[0]), "+f"(c[1]), "+f"(c[2]), "+f"(c[3])
        : "r"(a[0]), "r"(a[1]), "r"(a[2]), "r"(a[3]), "r"(b[0]), "r"(b[1]));
}

__device__ __forceinline__ void cp16(uint32_t dst, const void* src) {
    asm volatile("cp.async.cg.shared.global [%0], [%1], 16;\n" :: "r"(dst), "l"(src));
}

// ---------------------------------------------------------------------------
// GEMM config: 128 thr / 4 warps / warp tile 64x64 (measured-best geometry),
// NOW 2-stage cp.async (73.7KB smem) + regs capped at 168 -> 3 CTAs/SM
// = 12 warps/SM = 3 warps/SMSP (up from 2).
// 2-stage requires a second barrier per K-chunk (load slot == compute slot);
// the per-CTA serialization is hidden by the 3rd co-resident CTA.
// ---------------------------------------------------------------------------
#define TROW 36                        // padded row stride (floats)
#define GBOFF (128 * TROW)             // B offset within a stage (floats)
#define GSSTR ((128 + 128) * TROW)     // floats per stage
#define SMEMG (2 * GSSTR * 4)          // 73728 bytes (2 stages)

#define GEMM_PROLOG()                                                         \
    extern __shared__ float sm[];                                             \
    const uint32_t sb = (uint32_t)__cvta_generic_to_shared(sm);               \
    const int tid  = threadIdx.x;                                             \
    const int lane = tid & 31;                                                \
    const int wid  = tid >> 5;                                                \
    const int wm   = wid & 1;                                                 \
    const int wn   = wid >> 1;                                                \
    const int lrow = tid >> 3;                                                \
    const int kq   = (tid & 7) * 4;

#define LOAD_STAGE(kc, slot) do {                                             \
        const uint32_t _so = (uint32_t)(slot) * (GSSTR * 4);                  \
        const int _kb = (kc) * 32;                                            \
        _Pragma("unroll")                                                     \
        for (int i = 0; i < 8; i++) {                                         \
            int gr = row0 + lrow + 16 * i; if (gr > M - 1) gr = M - 1;        \
            cp16(aS0 + _so + (uint32_t)(16 * i * TROW * 4),                   \
                 aBase + (size_t)gr * lda + _kb);                             \
            cp16(bS0 + _so + (uint32_t)(16 * i * TROW * 4),                   \
                 bBase + (size_t)(16 * i) * ldb + _kb);                       \
        }                                                                     \
        asm volatile("cp.async.commit_group;" ::);                            \
    } while (0)

#define GEMM_MAINLOOP()                                                       \
    float acc[4][8][4];                                                       \
    _Pragma("unroll")                                                         \
    for (int i = 0; i < 4; i++)                                               \
        _Pragma("unroll")                                                     \
        for (int j = 0; j < 8; j++)                                           \
            _Pragma("unroll")                                                 \
            for (int q = 0; q < 4; q++) acc[i][j][q] = 0.f;                   \
    const int KT = K >> 5;                                                    \
    LOAD_STAGE(0, 0);                                                         \
    LOAD_STAGE(1, 1);                                                         \
    const int r     = lane >> 2;                                              \
    const int cfrag = lane & 3;                                               \
    for (int kt = 0; kt < KT; kt++) {                                         \
        asm volatile("cp.async.wait_group 1;" ::: "memory");                  \
        __syncthreads();                                                      \
        const int st = (kt & 1) * GSSTR;                                      \
        _Pragma("unroll")                                                     \
        for (int kk = 0; kk < 4; kk++) {                                      \
            const int kb = kk * 8 + cfrag;                                    \
            uint32_t a[4][4], b[8][2];                                        \
            _Pragma("unroll")                                                 \
            for (int mi = 0; mi < 4; mi++) {                                  \
                int base = st + (wm * 64 + mi * 16 + r) * TROW + kb;          \
                a[mi][0] = f2tf32(sm[base]);                                  \
                a[mi][1] = f2tf32(sm[base + 8 * TROW]);                       \
                a[mi][2] = f2tf32(sm[base + 4]);                              \
                a[mi][3] = f2tf32(sm[base + 8 * TROW + 4]);                   \
            }                                                                 \
            _Pragma("unroll")                                                 \
            for (int nj = 0; nj < 8; nj++) {                                  \
                int base = st + GBOFF + (wn * 64 + nj * 8 + r) * TROW + kb;   \
                b[nj][0] = __float_as_uint(sm[base]);                         \
                b[nj][1] = __float_as_uint(sm[base + 4]);                     \
            }                                                                 \
            _Pragma("unroll")                                                 \
            for (int mi = 0; mi < 4; mi++)                                    \
                _Pragma("unroll")                                             \
                for (int nj = 0; nj < 8; nj++)                                \
                    mma_tf32(acc[mi][nj], a[mi], b[nj]);                      \
        }                                                                     \
        __syncthreads();   /* all warps done reading slot kt&1 */             \
        if (kt + 2 < KT) {                                                    \
            LOAD_STAGE(kt + 2, kt & 1);                                       \
        } else {                                                              \
            asm volatile("cp.async.commit_group;" ::);                        \
        }                                                                     \
    }

// ---------------------------------------------------------------------------
// Dual-source big GEMM: one launch computing both
//   [A1|A2]  = article_x   @ Wfa^T + bfa   (grid.y in [0, halves))
//   [C1|CR3] = community_x @ Wcc^T + bcc   (grid.y in [halves, 2*halves))
// ---------------------------------------------------------------------------
__global__ __launch_bounds__(128, 3)
void tf32_gemm_dual_kernel(const float* __restrict__ Aa,
                           const float* __restrict__ Ab,
                           const float* __restrict__ Bta,
                           const float* __restrict__ Btb,
                           const float* __restrict__ biasa,
                           const float* __restrict__ biasb,
                           float* __restrict__ Ca, float* __restrict__ C2a,
                           float* __restrict__ Cb, float* __restrict__ C2b,
                           int halves, int M)
{
    GEMM_PROLOG();
    const int half = (blockIdx.y >= halves) ? 1 : 0;
    const int by   = blockIdx.y - half * halves;
    const int row0 = by * 128;
    const int col0 = blockIdx.x * 128;
    const int lda = F_IN, ldb = F_IN, K = F_IN;

    const float* A    = half ? Ab : Aa;
    const float* Bt   = half ? Btb : Bta;
    const float* bias = half ? biasb : biasa;
    float* C  = half ? Cb : Ca;
    float* C2 = half ? C2b : C2a;

    const float*   aBase = A + kq;
    const float*   bBase = Bt + (size_t)(col0 + lrow) * ldb + kq;
    const uint32_t aS0 = sb + (uint32_t)((lrow * TROW + kq) * 4);
    const uint32_t bS0 = sb + (uint32_t)((GBOFF + lrow * TROW + kq) * 4);

    GEMM_MAINLOOP();

#pragma unroll
    for (int mi = 0; mi < 4; mi++) {
#pragma unroll
        for (int halfr = 0; halfr < 2; halfr++) {
            int row = row0 + wm * 64 + mi * 16 + r + halfr * 8;
            if (row >= M) continue;
#pragma unroll
            for (int nj = 0; nj < 8; nj++) {
                int c = col0 + wn * 64 + nj * 8 + cfrag * 2;
                float v0 = acc[mi][nj][halfr * 2 + 0] + bias[c];
                float v1 = acc[mi][nj][halfr * 2 + 1] + bias[c + 1];
                float2 o = make_float2(v0, v1);
                if (c >= 256)
                    *(float2*)&C2[(size_t)row * 256 + (c - 256)] = o;
                else
                    *(float2*)&C[(size_t)row * 256 + c] = o;
            }
        }
    }
}

// ---------------------------------------------------------------------------
// Generic tf32 GEMM (small GEMMs): C = A @ Bt^T (+bias)(+D)(relu)
// ---------------------------------------------------------------------------
__global__ __launch_bounds__(128, 3)
void tf32_gemm_kernel(const float* __restrict__ A, int lda,
                      const float* __restrict__ Bt, int ldb,
                      float* __restrict__ C, int ldc,
                      const float* __restrict__ bias,
                      const float* __restrict__ D, int ldd,
                      int M, int K, int relu)
{
    GEMM_PROLOG();
    const int row0 = blockIdx.y * 128;
    const int col0 = blockIdx.x * 128;

    const float*   aBase = A + kq;
    const float*   bBase = Bt + (size_t)(col0 + lrow) * ldb + kq;
    const uint32_t aS0 = sb + (uint32_t)((lrow * TROW + kq) * 4);
    const uint32_t bS0 = sb + (uint32_t)((GBOFF + lrow * TROW + kq) * 4);

    GEMM_MAINLOOP();

#pragma unroll
    for (int mi = 0; mi < 4; mi++) {
#pragma unroll
        for (int halfr = 0; halfr < 2; halfr++) {
            int row = row0 + wm * 64 + mi * 16 + r + halfr * 8;
            if (row >= M) continue;
#pragma unroll
            for (int nj = 0; nj < 8; nj++) {
                int c = col0 + wn * 64 + nj * 8 + cfrag * 2;
                float v0 = acc[mi][nj][halfr * 2 + 0];
                float v1 = acc[mi][nj][halfr * 2 + 1];
                if (bias) { v0 += bias[c]; v1 += bias[c + 1]; }
                if (D) {
                    float2 d = *(const float2*)&D[(size_t)row * ldd + c];
                    v0 += d.x; v1 += d.y;
                }
                if (relu) { v0 = fmaxf(v0, 0.f); v1 = fmaxf(v1, 0.f); }
                *(float2*)&C[(size_t)row * ldc + c] = make_float2(v0, v1);
            }
        }
    }
}

// ---------------------------------------------------------------------------
// Fold: all three PROJ-contraction weight GEMMs in one launch (grid.z = 3).
// ---------------------------------------------------------------------------
#define FBK 16

__global__ __launch_bounds__(256)
void fold_all_kernel(const float* __restrict__ W1, const float* __restrict__ Wl1,
                     const float* __restrict__ Wl2,
                     const float* __restrict__ W2, const float* __restrict__ Wr1,
                     float* __restrict__ Wfa, float* __restrict__ Wcc)
{
    const int z = blockIdx.z;
    const float* A = (z < 2) ? W1 : W2;
    const float* B = (z == 0) ? Wl1 : (z == 1) ? Wl2 : Wr1;
    float* C  = (z == 0) ? Wfa : (z == 1) ? (Wfa + 256) : Wcc;
    const int ldc = (z < 2) ? 512 : 256;

    __shared__ float As[FBK][64];
    __shared__ float Bs[FBK][64];
    const int tid = threadIdx.x;
    const int tx = tid & 15, ty = tid >> 4;
    const int row0 = blockIdx.y * 64, col0 = blockIdx.x * 64;
    const int aRow = tid >> 2, aK = (tid & 3) * 4;
    const int bK = tid >> 4, bCol = (tid & 15) * 4;
    const float* Aptr = A + (size_t)(row0 + aRow) * PROJ + aK;
    const float* Bptr = B + (size_t)bK * HID + col0 + bCol;

    float acc[4][4];
#pragma unroll
    for (int i = 0; i < 4; i++)
#pragma unroll
        for (int j = 0; j < 4; j++) acc[i][j] = 0.f;

    for (int k0 = 0; k0 < PROJ; k0 += FBK) {
        float4 av = *(const float4*)Aptr;
        float4 bv = *(const float4*)Bptr;
        Aptr += FBK; Bptr += (size_t)FBK * HID;
        As[aK + 0][aRow] = av.x; As[aK + 1][aRow] = av.y;
        As[aK + 2][aRow] = av.z; As[aK + 3][aRow] = av.w;
        *(float4*)&Bs[bK][bCol] = bv;
        __syncthreads();
#pragma unroll
        for (int kk = 0; kk < FBK; kk++) {
            float4 ra = *(const float4*)&As[kk][ty * 4];
            float4 rb = *(const float4*)&Bs[kk][tx * 4];
            acc[0][0] += ra.x * rb.x; acc[0][1] += ra.x * rb.y;
            acc[0][2] += ra.x * rb.z; acc[0][3] += ra.x * rb.w;
            acc[1][0] += ra.y * rb.x; acc[1][1] += ra.y * rb.y;
            acc[1][2] += ra.y * rb.z; acc[1][3] += ra.y * rb.w;
            acc[2][0] += ra.z * rb.x; acc[2][1] += ra.z * rb.y;
            acc[2][2] += ra.z * rb.z; acc[2][3] += ra.z * rb.w;
            acc[3][0] += ra.w * rb.x; acc[3][1] += ra.w * rb.y;
            acc[3][2] += ra.w * rb.z; acc[3][3] += ra.w * rb.w;
        }
        __syncthreads();
    }
#pragma unroll
    for (int i = 0; i < 4; i++) {
        int rr = row0 + ty * 4 + i;
        *(float4*)&C[(size_t)rr * ldc + col0 + tx * 4] =
            make_float4(acc[i][0], acc[i][1], acc[i][2], acc[i][3]);
    }
}

// ---------------------------------------------------------------------------
// Mega-prep: all transposes (+tf32 rounding) and both bias fusions, one launch.
// ---------------------------------------------------------------------------
__device__ __forceinline__ void transpose_tile(const float* __restrict__ in, int C_in,
                                               float* __restrict__ out, int ld_out,
                                               int row_off, int b)
{
    __shared__ float t[32][33];
    const int tx = threadIdx.x & 31, ty = threadIdx.x >> 5;   // 32 x 8
    const int tilesX = C_in >> 5;
    const int bx = (b % tilesX) * 32;
    const int by = (b / tilesX) * 32;
#pragma unroll
    for (int i = 0; i < 32; i += 8)
        t[ty + i][tx] = in[(size_t)(by + ty + i) * C_in + bx + tx];
    __syncthreads();
#pragma unroll
    for (int i = 0; i < 32; i += 8)
        out[(size_t)(row_off + bx + ty + i) * ld_out + by + tx] =
            __uint_as_float(f2tf32(t[tx][ty + i]));
}

__global__ void prep_all_kernel(const float* __restrict__ Wfa,
                                const float* __restrict__ Wcc,
                                const float* __restrict__ Wr3,
                                const float* __restrict__ Wr2,
                                const float* __restrict__ Wl3,
                                const float* __restrict__ W3,
                                const float* __restrict__ b1,
                                const float* __restrict__ Wl1,
                                const float* __restrict__ Wl2,
                                const float* __restrict__ b2,
                                const float* __restrict__ Wr1,
                                const float* __restrict__ bl1,
                                const float* __restrict__ bl3,
                                float* __restrict__ Wfa_t,
                                float* __restrict__ Wcc_t,
                                float* __restrict__ Wr2_t,
                                float* __restrict__ Wl3_t,
                                float* __restrict__ W3_t,
                                float* __restrict__ bfa,
                                float* __restrict__ bcc)
{
    const int b = blockIdx.x;
    if (b < 384) {                       // Wfa [768][512] -> Wfa_t [512][768]
        transpose_tile(Wfa, 512, Wfa_t, F_IN, 0, b);
    } else if (b < 576) {                // Wcc [768][256] -> Wcc_t rows 0-255
        transpose_tile(Wcc, 256, Wcc_t, F_IN, 0, b - 384);
    } else if (b < 768) {                // Wr3 [768][256] -> Wcc_t rows 256-511
        transpose_tile(Wr3, 256, Wcc_t, F_IN, 256, b - 576);
    } else if (b < 832) {                // Wr2 [256][256]
        transpose_tile(Wr2, 256, Wr2_t, HID, 0, b - 768);
    } else if (b < 896) {                // Wl3 [256][256]
        transpose_tile(Wl3, 256, Wl3_t, HID, 0, b - 832);
    } else if (b < 928) {                // W3 [256][128] -> W3_t [128][256]
        transpose_tile(W3, 128, W3_t, HID, 0, b - 896);
    } else if (b == 928) {               // bfa = b1 @ [Wl1 | Wl2]
        int j = threadIdx.x;
        float s1 = 0.f, s2 = 0.f;
        for (int k = 0; k < PROJ; k++) {
            float b1k = b1[k];
            s1 += b1k * Wl1[(size_t)k * HID + j];
            s2 += b1k * Wl2[(size_t)k * HID + j];
        }
        bfa[j] = s1;
        bfa[256 + j] = s2;
    } else {                             // bcc = [b2 @ Wr1 + bl1 | bl3]
        int j = threadIdx.x;
        float s3 = 0.f;
        for (int k = 0; k < PROJ; k++) s3 += b2[k] * Wr1[(size_t)k * HID + j];
        bcc[j] = s3 + bl1[j];
        bcc[256 + j] = bl3[j];
    }
}

// ---------------------------------------------------------------------------
// CSR build: merged across the 3 edge sets
// ---------------------------------------------------------------------------
__global__ void zero_cnt_kernel(int* __restrict__ cnt)
{
    int i = blockIdx.x * blockDim.x + threadIdx.x;
    if (i < 3 * N_NODES) cnt[i] = 0;
}

__global__ void hist_all_kernel(const int* __restrict__ d0, int E0,
                                const int* __restrict__ d1, int E1,
                                const int* __restrict__ d2, int E2,
                                int* __restrict__ cnt)
{
    const int z = blockIdx.z;
    const int e = blockIdx.x * blockDim.x + threadIdx.x;
    const int E = (z == 0) ? E0 : (z == 1) ? E1 : E2;
    if (e >= E) return;
    const int* dst = (z == 0) ? d0 : (z == 1) ? d1 : d2;
    atomicAdd(&cnt[z * N_NODES + dst[e]], 1);
}

__global__ void exscan_all_kernel(int* __restrict__ cnt,
                                  int* __restrict__ r0,
                                  int* __restrict__ r1,
                                  int* __restrict__ r2)
{
    __shared__ int wsum[32];
    __shared__ int carry;
    const int z = blockIdx.x;
    int* cz = cnt + z * N_NODES;
    int* rowptr = (z == 0) ? r0 : (z == 1) ? r1 : r2;
    int tid = threadIdx.x, lane = tid & 31, warp = tid >> 5;
    if (tid == 0) carry = 0;
    __syncthreads();
    for (int base = 0; base < N_NODES; base += 1024) {
        int idx = base + tid;
        int v = (idx < N_NODES) ? cz[idx] : 0;
        int s = v;
#pragma unroll
        for (int off = 1; off < 32; off <<= 1) {
            int t = __shfl_up_sync(0xffffffffu, s, off);
            if (lane >= off) s += t;
        }
        if (lane == 31) wsum[warp] = s;
        __syncthreads();
        if (warp == 0) {
            int w = wsum[lane];
#pragma unroll
            for (int off = 1; off < 32; off <<= 1) {
                int t = __shfl_up_sync(0xffffffffu, w, off);
                if (lane >= off) w += t;
            }
            wsum[lane] = w;
        }
        __syncthreads();
        int woff = warp ? wsum[warp - 1] : 0;
        int myc = carry;
        int total = wsum[31];
        if (idx < N_NODES) {
            int ex = myc + woff + s - v;
            rowptr[idx] = ex;
            cz[idx] = ex;            // fill cursor
        }
        __syncthreads();
        if (tid == 0) carry = myc + total;
        __syncthreads();
    }
    if (tid == 0) rowptr[N_NODES] = carry;
}

__global__ void fill_all_kernel(const int* __restrict__ e0, int E0,
                                const int* __restrict__ e1, int E1,
                                const int* __restrict__ e2, int E2,
                                int* __restrict__ cnt,
                                int* __restrict__ c0,
                                int* __restrict__ c1,
                                int* __restrict__ c2)
{
    const int z = blockIdx.z;
    const int e = blockIdx.x * blockDim.x + threadIdx.x;
    const int E = (z == 0) ? E0 : (z == 1) ? E1 : E2;
    if (e >= E) return;
    const int* edges = (z == 0) ? e0 : (z == 1) ? e1 : e2;
    int* col = (z == 0) ? c0 : (z == 1) ? c1 : c2;
    int src = edges[e];
    int dst = edges[E + e];
    int p = atomicAdd(&cnt[z * N_NODES + dst], 1);
    col[p] = src;
}

// ---------------------------------------------------------------------------
// CSR mean aggregation, vectorized: 4 nodes/block, 64 threads/node, float4.
// grid.y = 2 variant runs two independent jobs in one launch.
// ---------------------------------------------------------------------------
__device__ __forceinline__ void csr_mean_body(const int* __restrict__ rowptr,
                                              const int* __restrict__ col,
                                              const float* __restrict__ feat,
                                              const float* __restrict__ add,
                                              float* __restrict__ out, int relu)
{
    const int sub  = threadIdx.x >> 6;
    const int j    = threadIdx.x & 63;
    const int node = blockIdx.x * 4 + sub;
    if (node >= N_NODES) return;

    const float4* f4 = (const float4*)feat;
    int s = rowptr[node], e = rowptr[node + 1];

    float4 acc0 = make_float4(0.f, 0.f, 0.f, 0.f);
    float4 acc1 = make_float4(0.f, 0.f, 0.f, 0.f);
    int k = s;
    for (; k + 2 <= e; k += 2) {
        int c0 = col[k], c1 = col[k + 1];
        float4 v0 = f4[(size_t)c0 * 64 + j];
        float4 v1 = f4[(size_t)c1 * 64 + j];
        acc0.x += v0.x; acc0.y += v0.y; acc0.z += v0.z; acc0.w += v0.w;
        acc1.x += v1.x; acc1.y += v1.y; acc1.z += v1.z; acc1.w += v1.w;
    }
    if (k < e) {
        float4 v = f4[(size_t)col[k] * 64 + j];
        acc0.x += v.x; acc0.y += v.y; acc0.z += v.z; acc0.w += v.w;
    }
    float inv = 1.f / fmaxf((float)(e - s), 1.f);
    float4 m;
    m.x = (acc0.x + acc1.x) * inv;
    m.y = (acc0.y + acc1.y) * inv;
    m.z = (acc0.z + acc1.z) * inv;
    m.w = (acc0.w + acc1.w) * inv;
    if (add) {
        float4 a = ((const float4*)add)[(size_t)node * 64 + j];
        m.x += a.x; m.y += a.y; m.z += a.z; m.w += a.w;
    }
    if (relu) {
        m.x = fmaxf(m.x, 0.f); m.y = fmaxf(m.y, 0.f);
        m.z = fmaxf(m.z, 0.f); m.w = fmaxf(m.w, 0.f);
    }
    ((float4*)out)[(size_t)node * 64 + j] = m;
}

__global__ __launch_bounds__(256)
void csr_mean_kernel(const int* __restrict__ rowptr, const int* __restrict__ col,
                     const float* __restrict__ feat,
                     const float* __restrict__ add,
                     float* __restrict__ out, int relu)
{
    csr_mean_body(rowptr, col, feat, add, out, relu);
}

// Merged conv1+conv2-mean: grid.y==0 -> h1 = relu(mean_wb(A1)+C1);
//                          grid.y==1 -> M2 = mean_mb(A2)
__global__ __launch_bounds__(256)
void csr_mean2_kernel(const int* __restrict__ rp0, const int* __restrict__ col0,
                      const float* __restrict__ A1, const float* __restrict__ C1,
                      float* __restrict__ h1,
                      const int* __restrict__ rp1, const int* __restrict__ col1,
                      const float* __restrict__ A2, float* __restrict__ M2)
{
    if (blockIdx.y == 0)
        csr_mean_body(rp0, col0, A1, C1, h1, 1);
    else
        csr_mean_body(rp1, col1, A2, nullptr, M2, 0);
}

// ---------------------------------------------------------------------------
// Host orchestration
// ---------------------------------------------------------------------------
static void launch_tf32(const float* A, int lda, const float* Bt, int ldb,
                        float* C, int ldc, const float* bias,
                        const float* D, int ldd, int M, int N, int K, int relu)
{
    dim3 grid(N / 128, (M + 127) / 128);
    tf32_gemm_kernel<<<grid, 128, SMEMG>>>(A, lda, Bt, ldb, C, ldc,
                                           bias, D, ldd, M, K, relu);
}

extern "C" void kernel_launch(void* const* d_in, const int* in_sizes, int n_in,
                              void* d_out, int out_size)
{
    const float* article_x   = (const float*)d_in[0];
    const float* community_x = (const float*)d_in[1];
    const int* e_wb  = (const int*)d_in[2];
    const int* e_mb  = (const int*)d_in[3];
    const int* e_int = (const int*)d_in[4];
    const float* W1 = (const float*)d_in[5];
    const float* b1 = (const float*)d_in[6];
    const float* W2 = (const float*)d_in[7];
    const float* b2 = (const float*)d_in[8];
    const float* Wl1 = (const float*)d_in[9];
    const float* bl1 = (const float*)d_in[10];
    const float* Wr1 = (const float*)d_in[11];
    const float* Wl2 = (const float*)d_in[12];
    const float* bl2 = (const float*)d_in[13];
    const float* Wr2 = (const float*)d_in[14];
    const float* Wl3 = (const float*)d_in[15];
    const float* bl3 = (const float*)d_in[16];
    const float* Wr3 = (const float*)d_in[17];
    const float* W3  = (const float*)d_in[18];
    const float* b3  = (const float*)d_in[19];

    const int E_wb  = in_sizes[2] / 2;
    const int E_mb  = in_sizes[3] / 2;
    const int E_int = in_sizes[4] / 2;

    cudaFuncSetAttribute(tf32_gemm_dual_kernel,
                         cudaFuncAttributeMaxDynamicSharedMemorySize, SMEMG);
    cudaFuncSetAttribute(tf32_gemm_kernel,
                         cudaFuncAttributeMaxDynamicSharedMemorySize, SMEMG);

    float *A1, *A2, *C1, *CR3, *h1, *M2, *h2, *g2, *h3;
    float *Wfa, *Wcc, *Wfa_t, *Wcc_t, *Wr2_t, *Wl3_t, *W3_t, *bfa, *bcc;
    int *rp0, *rp1, *rp2, *cnt, *col0, *col1, *col2;
    cudaGetSymbolAddress((void**)&A1, g_A1);
    cudaGetSymbolAddress((void**)&A2, g_A2);
    cudaGetSymbolAddress((void**)&C1, g_C1);
    cudaGetSymbolAddress((void**)&CR3, g_CR3);
    cudaGetSymbolAddress((void**)&h1, g_h1);
    cudaGetSymbolAddress((void**)&M2, g_M2);
    cudaGetSymbolAddress((void**)&h2, g_h2);
    cudaGetSymbolAddress((void**)&g2, g_g2);
    cudaGetSymbolAddress((void**)&h3, g_h3);
    cudaGetSymbolAddress((void**)&Wfa, g_Wfa);
    cudaGetSymbolAddress((void**)&Wcc, g_Wcc);
    cudaGetSymbolAddress((void**)&Wfa_t, g_Wfa_t);
    cudaGetSymbolAddress((void**)&Wcc_t, g_Wcc_t);
    cudaGetSymbolAddress((void**)&Wr2_t, g_Wr2_t);
    cudaGetSymbolAddress((void**)&Wl3_t, g_Wl3_t);
    cudaGetSymbolAddress((void**)&W3_t, g_W3_t);
    cudaGetSymbolAddress((void**)&bfa, g_bfa);
    cudaGetSymbolAddress((void**)&bcc, g_bcc);
    cudaGetSymbolAddress((void**)&rp0, g_rp0);
    cudaGetSymbolAddress((void**)&rp1, g_rp1);
    cudaGetSymbolAddress((void**)&rp2, g_rp2);
    cudaGetSymbolAddress((void**)&cnt, g_cnt);
    cudaGetSymbolAddress((void**)&col0, g_col0);
    cudaGetSymbolAddress((void**)&col1, g_col1);
    cudaGetSymbolAddress((void**)&col2, g_col2);

    const int HALVES = (N_NODES + 127) / 128;      // 391
    const int EB = (MAXE + 255) / 256;             // edge blocks (max E)
    const int CMB = (N_NODES + 3) / 4;

    // [1] all weight folds (exact fp32)
    fold_all_kernel<<<dim3(4, 12, 3), 256>>>(W1, Wl1, Wl2, W2, Wr1, Wfa, Wcc);
    // [2] all transposes + bias fusions
    prep_all_kernel<<<930, 256>>>(Wfa, Wcc, Wr3, Wr2, Wl3, W3,
                                  b1, Wl1, Wl2, b2, Wr1, bl1, bl3,
                                  Wfa_t, Wcc_t, Wr2_t, Wl3_t, W3_t, bfa, bcc);
    // [3] zero histograms
    zero_cnt_kernel<<<(3 * N_NODES + 511) / 512, 512>>>(cnt);

    // [4] merged big GEMM: [A1|A2] and [C1|CR3]   (the launch ncu profiles)
    tf32_gemm_dual_kernel<<<dim3(4, 2 * HALVES), 128, SMEMG>>>(
        article_x, community_x, Wfa_t, Wcc_t, bfa, bcc,
        A1, A2, C1, CR3, HALVES, N_NODES);

    // [5..7] CSR builds (merged)
    hist_all_kernel<<<dim3(EB, 1, 3), 256>>>(e_wb + E_wb, E_wb,
                                             e_mb + E_mb, E_mb,
                                             e_int + E_int, E_int, cnt);
    exscan_all_kernel<<<3, 1024>>>(cnt, rp0, rp1, rp2);
    fill_all_kernel<<<dim3(EB, 1, 3), 256>>>(e_wb, E_wb, e_mb, E_mb,
                                             e_int, E_int, cnt,
                                             col0, col1, col2);

    // [8] conv1 + conv2-mean in one launch:
    //     h1 = relu(mean_wb(A1) + C1);  M2 = mean_mb(A2)
    csr_mean2_kernel<<<dim3(CMB, 2), 256>>>(rp0, col0, A1, C1, h1,
                                            rp1, col1, A2, M2);
    // [9] conv2: h2 = relu(h1 @ Wr2 + bl2 + M2)
    launch_tf32(h1, HID, Wr2_t, HID, h2, HID, bl2, M2, HID, N_NODES, 256, HID, 1);
    // [10] conv3 pre: g2 = h2 @ Wl3
    launch_tf32(h2, HID, Wl3_t, HID, g2, HID, nullptr, nullptr, 0, N_NODES, 256, HID, 0);
    // [11] conv3: h3 = relu(mean_int(g2) + CR3)
    csr_mean_kernel<<<CMB, 256>>>(rp2, col2, g2, CR3, h3, 1);
    // [12] out = h3 @ W3 + b3
    launch_tf32(h3, HID, W3_t, HID, (float*)d_out, OUT_D, b3, nullptr, 0,
                N_NODES, 128, HID, 0);
}

// round 13
// speedup vs baseline: 1.3767x; 1.3767x over previous
#include <cuda_runtime.h>
#include <cuda_fp16.h>
#include <cstddef>
#include <cstdint>

// ---------------------------------------------------------------------------
// Problem constants
// ---------------------------------------------------------------------------
#define N_NODES 50000
#define F_IN    768
#define PROJ    1024
#define HID     256
#define OUT_D   128
#define MAXE    500000

// ---------------------------------------------------------------------------
// Static device scratch
// ---------------------------------------------------------------------------
__device__ __half g_axh[(size_t)N_NODES * F_IN];     // fp16 article_x
__device__ __half g_cxh[(size_t)N_NODES * F_IN];     // fp16 community_x
__device__ __half g_A1 [(size_t)N_NODES * HID];
__device__ __half g_A2 [(size_t)N_NODES * HID];
__device__ __half g_C1 [(size_t)N_NODES * HID];
__device__ __half g_CR3[(size_t)N_NODES * HID];
__device__ __half g_h1 [(size_t)N_NODES * HID];
__device__ __half g_M2 [(size_t)N_NODES * HID];
__device__ __half g_h2 [(size_t)N_NODES * HID];
__device__ __half g_g2 [(size_t)N_NODES * HID];
__device__ __half g_h3 [(size_t)N_NODES * HID];
__device__ float  g_Wfa [(size_t)F_IN * 512];        // [W1@Wl1 | W1@Wl2] fp32
__device__ float  g_Wcc [(size_t)F_IN * 256];        // W2@Wr1 fp32
__device__ __half g_Wfah[(size_t)512 * F_IN];        // transposed fp16
__device__ __half g_Wcch[(size_t)512 * F_IN];        // rows 0-255 (W2@Wr1)^T, 256-511 Wr3^T
__device__ __half g_Wr2h[(size_t)HID * HID];
__device__ __half g_Wl3h[(size_t)HID * HID];
__device__ __half g_W3h [(size_t)OUT_D * HID];
__device__ float g_bfa[512];
__device__ float g_bcc[512];
__device__ int g_rp0[N_NODES + 1], g_rp1[N_NODES + 1], g_rp2[N_NODES + 1];
__device__ int g_cnt[3 * N_NODES];
__device__ int g_col0[MAXE], g_col1[MAXE], g_col2[MAXE];

// ---------------------------------------------------------------------------
// helpers
// ---------------------------------------------------------------------------
__device__ __forceinline__ void mma_f16(float* c, const uint32_t* a, const uint32_t* b) {
    asm volatile(
        "mma.sync.aligned.m16n8k16.row.col.f32.f16.f16.f32 "
        "{%0,%1,%2,%3}, {%4,%5,%6,%7}, {%8,%9}, {%0,%1,%2,%3};"
        : "+f"(c[0]), "+f"(c[1]), "+f"(c[2]), "+f"(c[3])
        : "r"(a[0]), "r"(a[1]), "r"(a[2]), "r"(a[3]), "r"(b[0]), "r"(b[1]));
}

__device__ __forceinline__ void cp16(uint32_t dst, const void* src) {
    asm volatile("cp.async.cg.shared.global [%0], [%1], 16;\n" :: "r"(dst), "l"(src));
}

// ---------------------------------------------------------------------------
// fp16 GEMM config: CTA tile 128x128, K-chunk 64 fp16, 128 thr / 4 warps,
// warp tile 64x64 (2x2), m16n8k16 -> 128 MMAs per 64-K chunk per warp.
// 2-stage cp.async, smem 73.7KB -> 3 CTAs/SM (regs capped 168).
// PADH=72 halves/row (144B): bank-conflict-free for frag LDS (4n+c distinct).
// ---------------------------------------------------------------------------
#define KCH  64
#define PADH 72
#define HBOFF (128 * PADH)            // B offset within stage (halves)
#define HSSTR (256 * PADH)            // halves per stage
#define SMEMH (2 * HSSTR * 2)         // 73728 bytes

#define GEMM_PROLOG()                                                         \
    extern __shared__ __half smh[];                                           \
    const uint32_t sbH = (uint32_t)__cvta_generic_to_shared(smh);             \
    const int tid  = threadIdx.x;                                             \
    const int lane = tid & 31;                                                \
    const int wid  = tid >> 5;                                                \
    const int wm   = wid & 1;                                                 \
    const int wn   = wid >> 1;                                                \
    const int lrow = tid >> 3;            /* 0..15 */                         \
    const int kq8  = (tid & 7) * 8;       /* halves, 16B chunk */

#define LOAD_STAGE_H(kc, slot) do {                                           \
        const uint32_t _so = (uint32_t)(slot) * (HSSTR * 2);                  \
        const int _kb = (kc) * KCH;                                           \
        _Pragma("unroll")                                                     \
        for (int i = 0; i < 8; i++) {                                         \
            int gr = row0 + lrow + 16 * i; if (gr > M - 1) gr = M - 1;        \
            cp16(aS0 + _so + (uint32_t)(16 * i * PADH * 2),                   \
                 aBase + (size_t)gr * lda + _kb);                             \
            cp16(bS0 + _so + (uint32_t)(16 * i * PADH * 2),                   \
                 bBase + (size_t)(16 * i) * ldb + _kb);                       \
        }                                                                     \
        asm volatile("cp.async.commit_group;" ::);                            \
    } while (0)

#define GEMM_MAINLOOP_H()                                                     \
    float acc[4][8][4];                                                       \
    _Pragma("unroll")                                                         \
    for (int i = 0; i < 4; i++)                                               \
        _Pragma("unroll")                                                     \
        for (int j = 0; j < 8; j++)                                           \
            _Pragma("unroll")                                                 \
            for (int q = 0; q < 4; q++) acc[i][j][q] = 0.f;                   \
    const int KT = K / KCH;                                                   \
    LOAD_STAGE_H(0, 0);                                                       \
    LOAD_STAGE_H(1, 1);                                                       \
    const int r     = lane >> 2;                                              \
    const int c2    = (lane & 3) * 2;                                         \
    for (int kt = 0; kt < KT; kt++) {                                         \
        asm volatile("cp.async.wait_group 1;" ::: "memory");                  \
        __syncthreads();                                                      \
        const int st = (kt & 1) * HSSTR;                                      \
        _Pragma("unroll")                                                     \
        for (int kk = 0; kk < 4; kk++) {                                      \
            const int kb = kk * 16 + c2;                                      \
            uint32_t a[4][4], b[8][2];                                        \
            _Pragma("unroll")                                                 \
            for (int mi = 0; mi < 4; mi++) {                                  \
                int base = st + (wm * 64 + mi * 16 + r) * PADH + kb;          \
                a[mi][0] = *(const uint32_t*)(smh + base);                    \
                a[mi][1] = *(const uint32_t*)(smh + base + 8 * PADH);         \
                a[mi][2] = *(const uint32_t*)(smh + base + 8);                \
                a[mi][3] = *(const uint32_t*)(smh + base + 8 * PADH + 8);     \
            }                                                                 \
            _Pragma("unroll")                                                 \
            for (int nj = 0; nj < 8; nj++) {                                  \
                int base = st + HBOFF + (wn * 64 + nj * 8 + r) * PADH + kb;   \
                b[nj][0] = *(const uint32_t*)(smh + base);                    \
                b[nj][1] = *(const uint32_t*)(smh + base + 8);                \
            }                                                                 \
            _Pragma("unroll")                                                 \
            for (int mi = 0; mi < 4; mi++)                                    \
                _Pragma("unroll")                                             \
                for (int nj = 0; nj < 8; nj++)                                \
                    mma_f16(acc[mi][nj], a[mi], b[nj]);                       \
        }                                                                     \
        __syncthreads();                                                      \
        if (kt + 2 < KT) {                                                    \
            LOAD_STAGE_H(kt + 2, kt & 1);                                     \
        } else {                                                              \
            asm volatile("cp.async.commit_group;" ::);                        \
        }                                                                     \
    }

// ---------------------------------------------------------------------------
// Dual-source big GEMM (fp16 in, fp16 out):
//   [A1|A2]  = axh @ Wfah^T + bfa   (grid.y < halves)
//   [C1|CR3] = cxh @ Wcch^T + bcc   (grid.y >= halves)
// ---------------------------------------------------------------------------
__global__ __launch_bounds__(128, 3)
void f16_gemm_dual_kernel(const __half* __restrict__ Aa,
                          const __half* __restrict__ Ab,
                          const __half* __restrict__ Bta,
                          const __half* __restrict__ Btb,
                          const float* __restrict__ biasa,
                          const float* __restrict__ biasb,
                          __half* __restrict__ Ca, __half* __restrict__ C2a,
                          __half* __restrict__ Cb, __half* __restrict__ C2b,
                          int halves, int M)
{
    GEMM_PROLOG();
    const int half_ = (blockIdx.y >= halves) ? 1 : 0;
    const int by    = blockIdx.y - half_ * halves;
    const int row0  = by * 128;
    const int col0  = blockIdx.x * 128;
    const int lda = F_IN, ldb = F_IN, K = F_IN;

    const __half* A    = half_ ? Ab : Aa;
    const __half* Bt   = half_ ? Btb : Bta;
    const float*  bias = half_ ? biasb : biasa;
    __half* C  = half_ ? Cb : Ca;
    __half* C2 = half_ ? C2b : C2a;

    const __half*  aBase = A + kq8;
    const __half*  bBase = Bt + (size_t)(col0 + lrow) * ldb + kq8;
    const uint32_t aS0 = sbH + (uint32_t)((lrow * PADH + kq8) * 2);
    const uint32_t bS0 = sbH + (uint32_t)((HBOFF + lrow * PADH + kq8) * 2);

    GEMM_MAINLOOP_H();

#pragma unroll
    for (int mi = 0; mi < 4; mi++) {
#pragma unroll
        for (int hr = 0; hr < 2; hr++) {
            int row = row0 + wm * 64 + mi * 16 + r + hr * 8;
            if (row >= M) continue;
#pragma unroll
            for (int nj = 0; nj < 8; nj++) {
                int c = col0 + wn * 64 + nj * 8 + c2;
                float v0 = acc[mi][nj][hr * 2 + 0] + bias[c];
                float v1 = acc[mi][nj][hr * 2 + 1] + bias[c + 1];
                __half2 o = __floats2half2_rn(v0, v1);
                if (c >= 256)
                    *(__half2*)&C2[(size_t)row * 256 + (c - 256)] = o;
                else
                    *(__half2*)&C[(size_t)row * 256 + c] = o;
            }
        }
    }
}

// ---------------------------------------------------------------------------
// Generic fp16 GEMM: C = A @ Bt^T (+bias fp32)(+D fp16)(relu)
// outh: 1 -> write fp16 (__half), 0 -> write fp32 (float)
// ---------------------------------------------------------------------------
__global__ __launch_bounds__(128, 3)
void f16_gemm_kernel(const __half* __restrict__ A, int lda,
                     const __half* __restrict__ Bt, int ldb,
                     void* __restrict__ Cv, int ldc,
                     const float* __restrict__ bias,
                     const __half* __restrict__ D, int ldd,
                     int M, int K, int relu, int outh)
{
    GEMM_PROLOG();
    const int row0 = blockIdx.y * 128;
    const int col0 = blockIdx.x * 128;

    const __half*  aBase = A + kq8;
    const __half*  bBase = Bt + (size_t)(col0 + lrow) * ldb + kq8;
    const uint32_t aS0 = sbH + (uint32_t)((lrow * PADH + kq8) * 2);
    const uint32_t bS0 = sbH + (uint32_t)((HBOFF + lrow * PADH + kq8) * 2);

    GEMM_MAINLOOP_H();

#pragma unroll
    for (int mi = 0; mi < 4; mi++) {
#pragma unroll
        for (int hr = 0; hr < 2; hr++) {
            int row = row0 + wm * 64 + mi * 16 + r + hr * 8;
            if (row >= M) continue;
#pragma unroll
            for (int nj = 0; nj < 8; nj++) {
                int c = col0 + wn * 64 + nj * 8 + c2;
                float v0 = acc[mi][nj][hr * 2 + 0];
                float v1 = acc[mi][nj][hr * 2 + 1];
                if (bias) { v0 += bias[c]; v1 += bias[c + 1]; }
                if (D) {
                    __half2 d2 = *(const __half2*)&D[(size_t)row * ldd + c];
                    float2 df = __half22float2(d2);
                    v0 += df.x; v1 += df.y;
                }
                if (relu) { v0 = fmaxf(v0, 0.f); v1 = fmaxf(v1, 0.f); }
                if (outh) {
                    *(__half2*)&((__half*)Cv)[(size_t)row * ldc + c] =
                        __floats2half2_rn(v0, v1);
                } else {
                    *(float2*)&((float*)Cv)[(size_t)row * ldc + c] =
                        make_float2(v0, v1);
                }
            }
        }
    }
}

// ---------------------------------------------------------------------------
// Fold: three PROJ-contraction weight GEMMs, one launch (grid.z = 3). Exact fp32.
// ---------------------------------------------------------------------------
#define FBK 16

__global__ __launch_bounds__(256)
void fold_all_kernel(const float* __restrict__ W1, const float* __restrict__ Wl1,
                     const float* __restrict__ Wl2,
                     const float* __restrict__ W2, const float* __restrict__ Wr1,
                     float* __restrict__ Wfa, float* __restrict__ Wcc)
{
    const int z = blockIdx.z;
    const float* A = (z < 2) ? W1 : W2;
    const float* B = (z == 0) ? Wl1 : (z == 1) ? Wl2 : Wr1;
    float* C  = (z == 0) ? Wfa : (z == 1) ? (Wfa + 256) : Wcc;
    const int ldc = (z < 2) ? 512 : 256;

    __shared__ float As[FBK][64];
    __shared__ float Bs[FBK][64];
    const int tid = threadIdx.x;
    const int tx = tid & 15, ty = tid >> 4;
    const int row0 = blockIdx.y * 64, col0 = blockIdx.x * 64;
    const int aRow = tid >> 2, aK = (tid & 3) * 4;
    const int bK = tid >> 4, bCol = (tid & 15) * 4;
    const float* Aptr = A + (size_t)(row0 + aRow) * PROJ + aK;
    const float* Bptr = B + (size_t)bK * HID + col0 + bCol;

    float acc[4][4];
#pragma unroll
    for (int i = 0; i < 4; i++)
#pragma unroll
        for (int j = 0; j < 4; j++) acc[i][j] = 0.f;

    for (int k0 = 0; k0 < PROJ; k0 += FBK) {
        float4 av = *(const float4*)Aptr;
        float4 bv = *(const float4*)Bptr;
        Aptr += FBK; Bptr += (size_t)FBK * HID;
        As[aK + 0][aRow] = av.x; As[aK + 1][aRow] = av.y;
        As[aK + 2][aRow] = av.z; As[aK + 3][aRow] = av.w;
        *(float4*)&Bs[bK][bCol] = bv;
        __syncthreads();
#pragma unroll
        for (int kk = 0; kk < FBK; kk++) {
            float4 ra = *(const float4*)&As[kk][ty * 4];
            float4 rb = *(const float4*)&Bs[kk][tx * 4];
            acc[0][0] += ra.x * rb.x; acc[0][1] += ra.x * rb.y;
            acc[0][2] += ra.x * rb.z; acc[0][3] += ra.x * rb.w;
            acc[1][0] += ra.y * rb.x; acc[1][1] += ra.y * rb.y;
            acc[1][2] += ra.y * rb.z; acc[1][3] += ra.y * rb.w;
            acc[2][0] += ra.z * rb.x; acc[2][1] += ra.z * rb.y;
            acc[2][2] += ra.z * rb.z; acc[2][3] += ra.z * rb.w;
            acc[3][0] += ra.w * rb.x; acc[3][1] += ra.w * rb.y;
            acc[3][2] += ra.w * rb.z; acc[3][3] += ra.w * rb.w;
        }
        __syncthreads();
    }
#pragma unroll
    for (int i = 0; i < 4; i++) {
        int rr = row0 + ty * 4 + i;
        *(float4*)&C[(size_t)rr * ldc + col0 + tx * 4] =
            make_float4(acc[i][0], acc[i][1], acc[i][2], acc[i][3]);
    }
}

// ---------------------------------------------------------------------------
// Mega-prep: all transposes (fp32 -> fp16) + both bias fusions, one launch.
// ---------------------------------------------------------------------------
__device__ __forceinline__ void transpose_tile_h(const float* __restrict__ in, int C_in,
                                                 __half* __restrict__ out, int ld_out,
                                                 int row_off, int b)
{
    __shared__ float t[32][33];
    const int tx = threadIdx.x & 31, ty = threadIdx.x >> 5;
    const int tilesX = C_in >> 5;
    const int bx = (b % tilesX) * 32;
    const int by = (b / tilesX) * 32;
#pragma unroll
    for (int i = 0; i < 32; i += 8)
        t[ty + i][tx] = in[(size_t)(by + ty + i) * C_in + bx + tx];
    __syncthreads();
#pragma unroll
    for (int i = 0; i < 32; i += 8)
        out[(size_t)(row_off + bx + ty + i) * ld_out + by + tx] =
            __float2half(t[tx][ty + i]);
}

__global__ void prep_all_kernel(const float* __restrict__ Wfa,
                                const float* __restrict__ Wcc,
                                const float* __restrict__ Wr3,
                                const float* __restrict__ Wr2,
                                const float* __restrict__ Wl3,
                                const float* __restrict__ W3,
                                const float* __restrict__ b1,
                                const float* __restrict__ Wl1,
                                const float* __restrict__ Wl2,
                                const float* __restrict__ b2,
                                const float* __restrict__ Wr1,
                                const float* __restrict__ bl1,
                                const float* __restrict__ bl3,
                                __half* __restrict__ Wfah,
                                __half* __restrict__ Wcch,
                                __half* __restrict__ Wr2h,
                                __half* __restrict__ Wl3h,
                                __half* __restrict__ W3h,
                                float* __restrict__ bfa,
                                float* __restrict__ bcc)
{
    const int b = blockIdx.x;
    if (b < 384) {                       // Wfa [768][512] -> Wfah [512][768]
        transpose_tile_h(Wfa, 512, Wfah, F_IN, 0, b);
    } else if (b < 576) {                // Wcc [768][256] -> Wcch rows 0-255
        transpose_tile_h(Wcc, 256, Wcch, F_IN, 0, b - 384);
    } else if (b < 768) {                // Wr3 [768][256] -> Wcch rows 256-511
        transpose_tile_h(Wr3, 256, Wcch, F_IN, 256, b - 576);
    } else if (b < 832) {                // Wr2 [256][256]
        transpose_tile_h(Wr2, 256, Wr2h, HID, 0, b - 768);
    } else if (b < 896) {                // Wl3 [256][256]
        transpose_tile_h(Wl3, 256, Wl3h, HID, 0, b - 832);
    } else if (b < 928) {                // W3 [256][128] -> W3h [128][256]
        transpose_tile_h(W3, 128, W3h, HID, 0, b - 896);
    } else if (b == 928) {               // bfa = b1 @ [Wl1 | Wl2]
        int j = threadIdx.x;
        float s1 = 0.f, s2 = 0.f;
        for (int k = 0; k < PROJ; k++) {
            float b1k = b1[k];
            s1 += b1k * Wl1[(size_t)k * HID + j];
            s2 += b1k * Wl2[(size_t)k * HID + j];
        }
        bfa[j] = s1;
        bfa[256 + j] = s2;
    } else {                             // bcc = [b2 @ Wr1 + bl1 | bl3]
        int j = threadIdx.x;
        float s3 = 0.f;
        for (int k = 0; k < PROJ; k++) s3 += b2[k] * Wr1[(size_t)k * HID + j];
        bcc[j] = s3 + bl1[j];
        bcc[256 + j] = bl3[j];
    }
}

// ---------------------------------------------------------------------------
// Convert inputs fp32 -> fp16 AND zero histograms, one launch.
// Blocks [0, 37500): article (float4 -> 4 fp16)
// Blocks [37500, 75000): community
// Blocks [75000, 75147): zero cnt (1024 ints each)
// ---------------------------------------------------------------------------
#define CONV_BLKS 37500   // 50000*768/4/256
#define ZERO_BLKS (((3 * N_NODES) + 1023) / 1024)

__global__ void convert_zero_kernel(const float* __restrict__ ax,
                                    const float* __restrict__ cx,
                                    __half* __restrict__ axh,
                                    __half* __restrict__ cxh,
                                    int* __restrict__ cnt)
{
    const int b = blockIdx.x;
    if (b < 2 * CONV_BLKS) {
        const float* src = (b < CONV_BLKS) ? ax : cx;
        __half* dst = (b < CONV_BLKS) ? axh : cxh;
        int i = (b % CONV_BLKS) * 256 + threadIdx.x;   // float4 index
        float4 v = ((const float4*)src)[i];
        __half2 h0 = __floats2half2_rn(v.x, v.y);
        __half2 h1 = __floats2half2_rn(v.z, v.w);
        uint2 o;
        o.x = *(uint32_t*)&h0;
        o.y = *(uint32_t*)&h1;
        ((uint2*)dst)[i] = o;
    } else {
        int i = (b - 2 * CONV_BLKS) * 1024 + threadIdx.x * 4;
        if (i < 3 * N_NODES) {
            cnt[i] = 0;
            if (i + 1 < 3 * N_NODES) cnt[i + 1] = 0;
            if (i + 2 < 3 * N_NODES) cnt[i + 2] = 0;
            if (i + 3 < 3 * N_NODES) cnt[i + 3] = 0;
        }
    }
}

// ---------------------------------------------------------------------------
// CSR build: merged across the 3 edge sets
// ---------------------------------------------------------------------------
__global__ void hist_all_kernel(const int* __restrict__ d0, int E0,
                                const int* __restrict__ d1, int E1,
                                const int* __restrict__ d2, int E2,
                                int* __restrict__ cnt)
{
    const int z = blockIdx.z;
    const int e = blockIdx.x * blockDim.x + threadIdx.x;
    const int E = (z == 0) ? E0 : (z == 1) ? E1 : E2;
    if (e >= E) return;
    const int* dst = (z == 0) ? d0 : (z == 1) ? d1 : d2;
    atomicAdd(&cnt[z * N_NODES + dst[e]], 1);
}

__global__ void exscan_all_kernel(int* __restrict__ cnt,
                                  int* __restrict__ r0,
                                  int* __restrict__ r1,
                                  int* __restrict__ r2)
{
    __shared__ int wsum[32];
    __shared__ int carry;
    const int z = blockIdx.x;
    int* cz = cnt + z * N_NODES;
    int* rowptr = (z == 0) ? r0 : (z == 1) ? r1 : r2;
    int tid = threadIdx.x, lane = tid & 31, warp = tid >> 5;
    if (tid == 0) carry = 0;
    __syncthreads();
    for (int base = 0; base < N_NODES; base += 1024) {
        int idx = base + tid;
        int v = (idx < N_NODES) ? cz[idx] : 0;
        int s = v;
#pragma unroll
        for (int off = 1; off < 32; off <<= 1) {
            int t = __shfl_up_sync(0xffffffffu, s, off);
            if (lane >= off) s += t;
        }
        if (lane == 31) wsum[warp] = s;
        __syncthreads();
        if (warp == 0) {
            int w = wsum[lane];
#pragma unroll
            for (int off = 1; off < 32; off <<= 1) {
                int t = __shfl_up_sync(0xffffffffu, w, off);
                if (lane >= off) w += t;
            }
            wsum[lane] = w;
        }
        __syncthreads();
        int woff = warp ? wsum[warp - 1] : 0;
        int myc = carry;
        int total = wsum[31];
        if (idx < N_NODES) {
            int ex = myc + woff + s - v;
            rowptr[idx] = ex;
            cz[idx] = ex;            // fill cursor
        }
        __syncthreads();
        if (tid == 0) carry = myc + total;
        __syncthreads();
    }
    if (tid == 0) rowptr[N_NODES] = carry;
}

__global__ void fill_all_kernel(const int* __restrict__ e0, int E0,
                                const int* __restrict__ e1, int E1,
                                const int* __restrict__ e2, int E2,
                                int* __restrict__ cnt,
                                int* __restrict__ c0,
                                int* __restrict__ c1,
                                int* __restrict__ c2)
{
    const int z = blockIdx.z;
    const int e = blockIdx.x * blockDim.x + threadIdx.x;
    const int E = (z == 0) ? E0 : (z == 1) ? E1 : E2;
    if (e >= E) return;
    const int* edges = (z == 0) ? e0 : (z == 1) ? e1 : e2;
    int* col = (z == 0) ? c0 : (z == 1) ? c1 : c2;
    int src = edges[e];
    int dst = edges[E + e];
    int p = atomicAdd(&cnt[z * N_NODES + dst], 1);
    col[p] = src;
}

// ---------------------------------------------------------------------------
// fp16 CSR mean aggregation: 4 nodes/block, 64 threads/node, 4 fp16 (uint2)
// per thread. fp32 accumulation inside.
// ---------------------------------------------------------------------------
__device__ __forceinline__ void csr_mean_body(const int* __restrict__ rowptr,
                                              const int* __restrict__ col,
                                              const __half* __restrict__ feat,
                                              const __half* __restrict__ add,
                                              __half* __restrict__ out, int relu)
{
    const int sub  = threadIdx.x >> 6;
    const int j    = threadIdx.x & 63;          // uint2 (4 fp16) index; row = 64 uint2
    const int node = blockIdx.x * 4 + sub;
    if (node >= N_NODES) return;

    const uint2* f2 = (const uint2*)feat;
    int s = rowptr[node], e = rowptr[node + 1];

    float4 acc = make_float4(0.f, 0.f, 0.f, 0.f);
    for (int k = s; k < e; k++) {
        uint2 v = f2[(size_t)col[k] * 64 + j];
        float2 p0 = __half22float2(*(__half2*)&v.x);
        float2 p1 = __half22float2(*(__half2*)&v.y);
        acc.x += p0.x; acc.y += p0.y; acc.z += p1.x; acc.w += p1.y;
    }
    float inv = 1.f / fmaxf((float)(e - s), 1.f);
    acc.x *= inv; acc.y *= inv; acc.z *= inv; acc.w *= inv;
    if (add) {
        uint2 a = ((const uint2*)add)[(size_t)node * 64 + j];
        float2 a0 = __half22float2(*(__half2*)&a.x);
        float2 a1 = __half22float2(*(__half2*)&a.y);
        acc.x += a0.x; acc.y += a0.y; acc.z += a1.x; acc.w += a1.y;
    }
    if (relu) {
        acc.x = fmaxf(acc.x, 0.f); acc.y = fmaxf(acc.y, 0.f);
        acc.z = fmaxf(acc.z, 0.f); acc.w = fmaxf(acc.w, 0.f);
    }
    __half2 o0 = __floats2half2_rn(acc.x, acc.y);
    __half2 o1 = __floats2half2_rn(acc.z, acc.w);
    uint2 o;
    o.x = *(uint32_t*)&o0;
    o.y = *(uint32_t*)&o1;
    ((uint2*)out)[(size_t)node * 64 + j] = o;
}

__global__ __launch_bounds__(256)
void csr_mean_kernel(const int* __restrict__ rowptr, const int* __restrict__ col,
                     const __half* __restrict__ feat,
                     const __half* __restrict__ add,
                     __half* __restrict__ out, int relu)
{
    csr_mean_body(rowptr, col, feat, add, out, relu);
}

__global__ __launch_bounds__(256)
void csr_mean2_kernel(const int* __restrict__ rp0, const int* __restrict__ col0,
                      const __half* __restrict__ A1, const __half* __restrict__ C1,
                      __half* __restrict__ h1,
                      const int* __restrict__ rp1, const int* __restrict__ col1,
                      const __half* __restrict__ A2, __half* __restrict__ M2)
{
    if (blockIdx.y == 0)
        csr_mean_body(rp0, col0, A1, C1, h1, 1);
    else
        csr_mean_body(rp1, col1, A2, nullptr, M2, 0);
}

// ---------------------------------------------------------------------------
// Host orchestration
// ---------------------------------------------------------------------------
static void launch_f16(const __half* A, int lda, const __half* Bt, int ldb,
                       void* C, int ldc, const float* bias,
                       const __half* D, int ldd, int M, int N, int K,
                       int relu, int outh)
{
    dim3 grid(N / 128, (M + 127) / 128);
    f16_gemm_kernel<<<grid, 128, SMEMH>>>(A, lda, Bt, ldb, C, ldc,
                                          bias, D, ldd, M, K, relu, outh);
}

extern "C" void kernel_launch(void* const* d_in, const int* in_sizes, int n_in,
                              void* d_out, int out_size)
{
    const float* article_x   = (const float*)d_in[0];
    const float* community_x = (const float*)d_in[1];
    const int* e_wb  = (const int*)d_in[2];
    const int* e_mb  = (const int*)d_in[3];
    const int* e_int = (const int*)d_in[4];
    const float* W1 = (const float*)d_in[5];
    const float* b1 = (const float*)d_in[6];
    const float* W2 = (const float*)d_in[7];
    const float* b2 = (const float*)d_in[8];
    const float* Wl1 = (const float*)d_in[9];
    const float* bl1 = (const float*)d_in[10];
    const float* Wr1 = (const float*)d_in[11];
    const float* Wl2 = (const float*)d_in[12];
    const float* bl2 = (const float*)d_in[13];
    const float* Wr2 = (const float*)d_in[14];
    const float* Wl3 = (const float*)d_in[15];
    const float* bl3 = (const float*)d_in[16];
    const float* Wr3 = (const float*)d_in[17];
    const float* W3  = (const float*)d_in[18];
    const float* b3  = (const float*)d_in[19];

    const int E_wb  = in_sizes[2] / 2;
    const int E_mb  = in_sizes[3] / 2;
    const int E_int = in_sizes[4] / 2;

    cudaFuncSetAttribute(f16_gemm_dual_kernel,
                         cudaFuncAttributeMaxDynamicSharedMemorySize, SMEMH);
    cudaFuncSetAttribute(f16_gemm_kernel,
                         cudaFuncAttributeMaxDynamicSharedMemorySize, SMEMH);

    __half *axh, *cxh, *A1, *A2, *C1, *CR3, *h1, *M2, *h2, *g2, *h3;
    __half *Wfah, *Wcch, *Wr2h, *Wl3h, *W3h;
    float *Wfa, *Wcc, *bfa, *bcc;
    int *rp0, *rp1, *rp2, *cnt, *col0, *col1, *col2;
    cudaGetSymbolAddress((void**)&axh, g_axh);
    cudaGetSymbolAddress((void**)&cxh, g_cxh);
    cudaGetSymbolAddress((void**)&A1, g_A1);
    cudaGetSymbolAddress((void**)&A2, g_A2);
    cudaGetSymbolAddress((void**)&C1, g_C1);
    cudaGetSymbolAddress((void**)&CR3, g_CR3);
    cudaGetSymbolAddress((void**)&h1, g_h1);
    cudaGetSymbolAddress((void**)&M2, g_M2);
    cudaGetSymbolAddress((void**)&h2, g_h2);
    cudaGetSymbolAddress((void**)&g2, g_g2);
    cudaGetSymbolAddress((void**)&h3, g_h3);
    cudaGetSymbolAddress((void**)&Wfa, g_Wfa);
    cudaGetSymbolAddress((void**)&Wcc, g_Wcc);
    cudaGetSymbolAddress((void**)&Wfah, g_Wfah);
    cudaGetSymbolAddress((void**)&Wcch, g_Wcch);
    cudaGetSymbolAddress((void**)&Wr2h, g_Wr2h);
    cudaGetSymbolAddress((void**)&Wl3h, g_Wl3h);
    cudaGetSymbolAddress((void**)&W3h, g_W3h);
    cudaGetSymbolAddress((void**)&bfa, g_bfa);
    cudaGetSymbolAddress((void**)&bcc, g_bcc);
    cudaGetSymbolAddress((void**)&rp0, g_rp0);
    cudaGetSymbolAddress((void**)&rp1, g_rp1);
    cudaGetSymbolAddress((void**)&rp2, g_rp2);
    cudaGetSymbolAddress((void**)&cnt, g_cnt);
    cudaGetSymbolAddress((void**)&col0, g_col0);
    cudaGetSymbolAddress((void**)&col1, g_col1);
    cudaGetSymbolAddress((void**)&col2, g_col2);

    const int HALVES = (N_NODES + 127) / 128;      // 391
    const int EB = (MAXE + 255) / 256;
    const int CMB = (N_NODES + 3) / 4;

    // [1] all weight folds (exact fp32)
    fold_all_kernel<<<dim3(4, 12, 3), 256>>>(W1, Wl1, Wl2, W2, Wr1, Wfa, Wcc);
    // [2] all transposes (-> fp16) + bias fusions
    prep_all_kernel<<<930, 256>>>(Wfa, Wcc, Wr3, Wr2, Wl3, W3,
                                  b1, Wl1, Wl2, b2, Wr1, bl1, bl3,
                                  Wfah, Wcch, Wr2h, Wl3h, W3h, bfa, bcc);
    // [3] convert inputs to fp16 + zero histograms
    convert_zero_kernel<<<2 * CONV_BLKS + ZERO_BLKS, 256>>>(
        article_x, community_x, axh, cxh, cnt);

    // [4] merged big GEMM (fp16): [A1|A2] and [C1|CR3]
    f16_gemm_dual_kernel<<<dim3(4, 2 * HALVES), 128, SMEMH>>>(
        axh, cxh, Wfah, Wcch, bfa, bcc, A1, A2, C1, CR3, HALVES, N_NODES);

    // [5..7] CSR builds (merged)
    hist_all_kernel<<<dim3(EB, 1, 3), 256>>>(e_wb + E_wb, E_wb,
                                             e_mb + E_mb, E_mb,
                                             e_int + E_int, E_int, cnt);
    exscan_all_kernel<<<3, 1024>>>(cnt, rp0, rp1, rp2);
    fill_all_kernel<<<dim3(EB, 1, 3), 256>>>(e_wb, E_wb, e_mb, E_mb,
                                             e_int, E_int, cnt,
                                             col0, col1, col2);

    // [8] conv1 + conv2-mean: h1 = relu(mean_wb(A1)+C1); M2 = mean_mb(A2)
    csr_mean2_kernel<<<dim3(CMB, 2), 256>>>(rp0, col0, A1, C1, h1,
                                            rp1, col1, A2, M2);
    // [9] conv2: h2 = relu(h1 @ Wr2 + bl2 + M2)   (fp16 out)
    launch_f16(h1, HID, Wr2h, HID, h2, HID, bl2, M2, HID, N_NODES, 256, HID, 1, 1);
    // [10] conv3 pre: g2 = h2 @ Wl3               (fp16 out)
    launch_f16(h2, HID, Wl3h, HID, g2, HID, nullptr, nullptr, 0, N_NODES, 256, HID, 0, 1);
    // [11] conv3: h3 = relu(mean_int(g2) + CR3)
    csr_mean_kernel<<<CMB, 256>>>(rp2, col2, g2, CR3, h3, 1);
    // [12] out = h3 @ W3 + b3                     (fp32 out)
    launch_f16(h3, HID, W3h, HID, d_out, OUT_D, b3, nullptr, 0, N_NODES, 128, HID, 0, 0);
}

// round 14
// speedup vs baseline: 1.4275x; 1.0369x over previous
#include <cuda_runtime.h>
#include <cuda_fp16.h>
#include <cstddef>
#include <cstdint>

// ---------------------------------------------------------------------------
// Problem constants
// ---------------------------------------------------------------------------
#define N_NODES 50000
#define F_IN    768
#define PROJ    1024
#define HID     256
#define OUT_D   128
#define MAXE    500000

// ---------------------------------------------------------------------------
// Static device scratch
// ---------------------------------------------------------------------------
__device__ __half g_axh[(size_t)N_NODES * F_IN];     // fp16 article_x
__device__ __half g_cxh[(size_t)N_NODES * F_IN];     // fp16 community_x
__device__ __half g_A1 [(size_t)N_NODES * HID];
__device__ __half g_A2 [(size_t)N_NODES * HID];
__device__ __half g_C1 [(size_t)N_NODES * HID];
__device__ __half g_CR3[(size_t)N_NODES * HID];
__device__ __half g_h1 [(size_t)N_NODES * HID];
__device__ __half g_M2 [(size_t)N_NODES * HID];
__device__ __half g_h2 [(size_t)N_NODES * HID];
__device__ __half g_g2 [(size_t)N_NODES * HID];
__device__ __half g_h3 [(size_t)N_NODES * HID];
__device__ float  g_Wfa [(size_t)F_IN * 512];        // [W1@Wl1 | W1@Wl2] fp32
__device__ float  g_Wcc [(size_t)F_IN * 256];        // W2@Wr1 fp32
__device__ __half g_Wfah[(size_t)512 * F_IN];        // transposed fp16
__device__ __half g_Wcch[(size_t)512 * F_IN];        // rows 0-255 (W2@Wr1)^T, 256-511 Wr3^T
__device__ __half g_Wr2h[(size_t)HID * HID];
__device__ __half g_Wl3h[(size_t)HID * HID];
__device__ __half g_W3h [(size_t)OUT_D * HID];
__device__ float g_bfa[512];
__device__ float g_bcc[512];
__device__ int g_rp0[N_NODES + 1], g_rp1[N_NODES + 1], g_rp2[N_NODES + 1];
__device__ int g_cnt[3 * N_NODES];
__device__ int g_col0[MAXE], g_col1[MAXE], g_col2[MAXE];

// ---------------------------------------------------------------------------
// helpers
// ---------------------------------------------------------------------------
__device__ __forceinline__ void mma_f16(float* c, const uint32_t* a, const uint32_t* b) {
    asm volatile(
        "mma.sync.aligned.m16n8k16.row.col.f32.f16.f16.f32 "
        "{%0,%1,%2,%3}, {%4,%5,%6,%7}, {%8,%9}, {%0,%1,%2,%3};"
        : "+f"(c[0]), "+f"(c[1]), "+f"(c[2]), "+f"(c[3])
        : "r"(a[0]), "r"(a[1]), "r"(a[2]), "r"(a[3]), "r"(b[0]), "r"(b[1]));
}

__device__ __forceinline__ void cp16(uint32_t dst, const void* src) {
    asm volatile("cp.async.cg.shared.global [%0], [%1], 16;\n" :: "r"(dst), "l"(src));
}

__device__ __forceinline__ void ldsm4(uint32_t* r, uint32_t addr) {
    asm volatile("ldmatrix.sync.aligned.m8n8.x4.shared.b16 {%0,%1,%2,%3}, [%4];"
        : "=r"(r[0]), "=r"(r[1]), "=r"(r[2]), "=r"(r[3]) : "r"(addr));
}

// ---------------------------------------------------------------------------
// fp16 GEMM config: CTA tile 128x128, K-chunk 64 fp16, 128 thr / 4 warps,
// warp tile 64x64 (2x2), m16n8k16, ldmatrix fragment loads.
// 2-stage cp.async, smem 73.7KB -> 3 CTAs/SM (regs capped 168).
// PADH=72 halves/row (144B): conflict-free for ldmatrix (banks 0,4,..28).
// ---------------------------------------------------------------------------
#define KCH  64
#define PADH 72
#define HBOFF (128 * PADH)            // B offset within stage (halves)
#define HSSTR (256 * PADH)            // halves per stage
#define SMEMH (2 * HSSTR * 2)         // 73728 bytes

#define GEMM_PROLOG()                                                         \
    extern __shared__ __half smh[];                                           \
    const uint32_t sbH = (uint32_t)__cvta_generic_to_shared(smh);             \
    const int tid  = threadIdx.x;                                             \
    const int lane = tid & 31;                                                \
    const int wid  = tid >> 5;                                                \
    const int wm   = wid & 1;                                                 \
    const int wn   = wid >> 1;                                                \
    const int lrow = tid >> 3;            /* 0..15 */                         \
    const int kq8  = (tid & 7) * 8;       /* halves, 16B chunk */

#define LOAD_STAGE_H(kc, slot) do {                                           \
        const uint32_t _so = (uint32_t)(slot) * (HSSTR * 2);                  \
        const int _kb = (kc) * KCH;                                           \
        _Pragma("unroll")                                                     \
        for (int i = 0; i < 8; i++) {                                         \
            int gr = row0 + lrow + 16 * i; if (gr > M - 1) gr = M - 1;        \
            cp16(aS0 + _so + (uint32_t)(16 * i * PADH * 2),                   \
                 aBase + (size_t)gr * lda + _kb);                             \
            cp16(bS0 + _so + (uint32_t)(16 * i * PADH * 2),                   \
                 bBase + (size_t)(16 * i) * ldb + _kb);                       \
        }                                                                     \
        asm volatile("cp.async.commit_group;" ::);                            \
    } while (0)

// ldmatrix per-lane source mapping:
//  A (16x16 tile per mi): tiles T0(r0-7,k0-7)->a0, T1(r8-15,k0-7)->a1,
//    T2(r0-7,k8-15)->a2, T3(r8-15,k8-15)->a3
//    lane -> row = lane&15, kofs = (lane>>4)*8
//  B (two n8 x k16 tiles per ldsm): order b[2p][0], b[2p][1], b[2p+1][0], b[2p+1][1]
//    lane -> row = (lane&7) + ((lane&16)>>1), kofs = ((lane>>3)&1)*8
#define GEMM_MAINLOOP_H()                                                     \
    float acc[4][8][4];                                                       \
    _Pragma("unroll")                                                         \
    for (int i = 0; i < 4; i++)                                               \
        _Pragma("unroll")                                                     \
        for (int j = 0; j < 8; j++)                                           \
            _Pragma("unroll")                                                 \
            for (int q = 0; q < 4; q++) acc[i][j][q] = 0.f;                   \
    const int KT = K / KCH;                                                   \
    LOAD_STAGE_H(0, 0);                                                       \
    LOAD_STAGE_H(1, 1);                                                       \
    const int r     = lane >> 2;                                              \
    const int c2    = (lane & 3) * 2;                                         \
    const uint32_t aF0 = sbH + (uint32_t)(((wm * 64 + (lane & 15)) * PADH     \
                                           + (lane >> 4) * 8) * 2);           \
    const uint32_t bF0 = sbH + (uint32_t)((HBOFF                              \
                         + (wn * 64 + (lane & 7) + ((lane & 16) >> 1)) * PADH \
                         + ((lane >> 3) & 1) * 8) * 2);                       \
    for (int kt = 0; kt < KT; kt++) {                                         \
        asm volatile("cp.async.wait_group 1;" ::: "memory");                  \
        __syncthreads();                                                      \
        const uint32_t stB = (uint32_t)((kt & 1) * (HSSTR * 2));              \
        _Pragma("unroll")                                                     \
        for (int kk = 0; kk < 4; kk++) {                                      \
            const uint32_t kbB = stB + (uint32_t)(kk * 32);                   \
            uint32_t a[4][4], b[8][2];                                        \
            _Pragma("unroll")                                                 \
            for (int mi = 0; mi < 4; mi++)                                    \
                ldsm4(a[mi], aF0 + kbB + (uint32_t)(mi * 16 * PADH * 2));     \
            _Pragma("unroll")                                                 \
            for (int p = 0; p < 4; p++)                                       \
                ldsm4(&b[2 * p][0], bF0 + kbB + (uint32_t)(p * 16 * PADH * 2));\
            _Pragma("unroll")                                                 \
            for (int mi = 0; mi < 4; mi++)                                    \
                _Pragma("unroll")                                             \
                for (int nj = 0; nj < 8; nj++)                                \
                    mma_f16(acc[mi][nj], a[mi], b[nj]);                       \
        }                                                                     \
        __syncthreads();                                                      \
        if (kt + 2 < KT) {                                                    \
            LOAD_STAGE_H(kt + 2, kt & 1);                                     \
        } else {                                                              \
            asm volatile("cp.async.commit_group;" ::);                        \
        }                                                                     \
    }

// ---------------------------------------------------------------------------
// Dual-source big GEMM (fp16 in, fp16 out):
//   [A1|A2]  = axh @ Wfah^T + bfa   (grid.y < halves)
//   [C1|CR3] = cxh @ Wcch^T + bcc   (grid.y >= halves)
// ---------------------------------------------------------------------------
__global__ __launch_bounds__(128, 3)
void f16_gemm_dual_kernel(const __half* __restrict__ Aa,
                          const __half* __restrict__ Ab,
                          const __half* __restrict__ Bta,
                          const __half* __restrict__ Btb,
                          const float* __restrict__ biasa,
                          const float* __restrict__ biasb,
                          __half* __restrict__ Ca, __half* __restrict__ C2a,
                          __half* __restrict__ Cb, __half* __restrict__ C2b,
                          int halves, int M)
{
    GEMM_PROLOG();
    const int half_ = (blockIdx.y >= halves) ? 1 : 0;
    const int by    = blockIdx.y - half_ * halves;
    const int row0  = by * 128;
    const int col0  = blockIdx.x * 128;
    const int lda = F_IN, ldb = F_IN, K = F_IN;

    const __half* A    = half_ ? Ab : Aa;
    const __half* Bt   = half_ ? Btb : Bta;
    const float*  bias = half_ ? biasb : biasa;
    __half* C  = half_ ? Cb : Ca;
    __half* C2 = half_ ? C2b : C2a;

    const __half*  aBase = A + kq8;
    const __half*  bBase = Bt + (size_t)(col0 + lrow) * ldb + kq8;
    const uint32_t aS0 = sbH + (uint32_t)((lrow * PADH + kq8) * 2);
    const uint32_t bS0 = sbH + (uint32_t)((HBOFF + lrow * PADH + kq8) * 2);

    GEMM_MAINLOOP_H();

#pragma unroll
    for (int mi = 0; mi < 4; mi++) {
#pragma unroll
        for (int hr = 0; hr < 2; hr++) {
            int row = row0 + wm * 64 + mi * 16 + r + hr * 8;
            if (row >= M) continue;
#pragma unroll
            for (int nj = 0; nj < 8; nj++) {
                int c = col0 + wn * 64 + nj * 8 + c2;
                float v0 = acc[mi][nj][hr * 2 + 0] + bias[c];
                float v1 = acc[mi][nj][hr * 2 + 1] + bias[c + 1];
                __half2 o = __floats2half2_rn(v0, v1);
                if (c >= 256)
                    *(__half2*)&C2[(size_t)row * 256 + (c - 256)] = o;
                else
                    *(__half2*)&C[(size_t)row * 256 + c] = o;
            }
        }
    }
}

// ---------------------------------------------------------------------------
// Generic fp16 GEMM: C = A @ Bt^T (+bias fp32)(+D fp16)(relu)
// outh: 1 -> write fp16 (__half), 0 -> write fp32 (float)
// ---------------------------------------------------------------------------
__global__ __launch_bounds__(128, 3)
void f16_gemm_kernel(const __half* __restrict__ A, int lda,
                     const __half* __restrict__ Bt, int ldb,
                     void* __restrict__ Cv, int ldc,
                     const float* __restrict__ bias,
                     const __half* __restrict__ D, int ldd,
                     int M, int K, int relu, int outh)
{
    GEMM_PROLOG();
    const int row0 = blockIdx.y * 128;
    const int col0 = blockIdx.x * 128;

    const __half*  aBase = A + kq8;
    const __half*  bBase = Bt + (size_t)(col0 + lrow) * ldb + kq8;
    const uint32_t aS0 = sbH + (uint32_t)((lrow * PADH + kq8) * 2);
    const uint32_t bS0 = sbH + (uint32_t)((HBOFF + lrow * PADH + kq8) * 2);

    GEMM_MAINLOOP_H();

#pragma unroll
    for (int mi = 0; mi < 4; mi++) {
#pragma unroll
        for (int hr = 0; hr < 2; hr++) {
            int row = row0 + wm * 64 + mi * 16 + r + hr * 8;
            if (row >= M) continue;
#pragma unroll
            for (int nj = 0; nj < 8; nj++) {
                int c = col0 + wn * 64 + nj * 8 + c2;
                float v0 = acc[mi][nj][hr * 2 + 0];
                float v1 = acc[mi][nj][hr * 2 + 1];
                if (bias) { v0 += bias[c]; v1 += bias[c + 1]; }
                if (D) {
                    __half2 d2 = *(const __half2*)&D[(size_t)row * ldd + c];
                    float2 df = __half22float2(d2);
                    v0 += df.x; v1 += df.y;
                }
                if (relu) { v0 = fmaxf(v0, 0.f); v1 = fmaxf(v1, 0.f); }
                if (outh) {
                    *(__half2*)&((__half*)Cv)[(size_t)row * ldc + c] =
                        __floats2half2_rn(v0, v1);
                } else {
                    *(float2*)&((float*)Cv)[(size_t)row * ldc + c] =
                        make_float2(v0, v1);
                }
            }
        }
    }
}

// ---------------------------------------------------------------------------
// Fold: three PROJ-contraction weight GEMMs, one launch (grid.z = 3). Exact fp32.
// ---------------------------------------------------------------------------
#define FBK 16

__global__ __launch_bounds__(256)
void fold_all_kernel(const float* __restrict__ W1, const float* __restrict__ Wl1,
                     const float* __restrict__ Wl2,
                     const float* __restrict__ W2, const float* __restrict__ Wr1,
                     float* __restrict__ Wfa, float* __restrict__ Wcc)
{
    const int z = blockIdx.z;
    const float* A = (z < 2) ? W1 : W2;
    const float* B = (z == 0) ? Wl1 : (z == 1) ? Wl2 : Wr1;
    float* C  = (z == 0) ? Wfa : (z == 1) ? (Wfa + 256) : Wcc;
    const int ldc = (z < 2) ? 512 : 256;

    __shared__ float As[FBK][64];
    __shared__ float Bs[FBK][64];
    const int tid = threadIdx.x;
    const int tx = tid & 15, ty = tid >> 4;
    const int row0 = blockIdx.y * 64, col0 = blockIdx.x * 64;
    const int aRow = tid >> 2, aK = (tid & 3) * 4;
    const int bK = tid >> 4, bCol = (tid & 15) * 4;
    const float* Aptr = A + (size_t)(row0 + aRow) * PROJ + aK;
    const float* Bptr = B + (size_t)bK * HID + col0 + bCol;

    float acc[4][4];
#pragma unroll
    for (int i = 0; i < 4; i++)
#pragma unroll
        for (int j = 0; j < 4; j++) acc[i][j] = 0.f;

    for (int k0 = 0; k0 < PROJ; k0 += FBK) {
        float4 av = *(const float4*)Aptr;
        float4 bv = *(const float4*)Bptr;
        Aptr += FBK; Bptr += (size_t)FBK * HID;
        As[aK + 0][aRow] = av.x; As[aK + 1][aRow] = av.y;
        As[aK + 2][aRow] = av.z; As[aK + 3][aRow] = av.w;
        *(float4*)&Bs[bK][bCol] = bv;
        __syncthreads();
#pragma unroll
        for (int kk = 0; kk < FBK; kk++) {
            float4 ra = *(const float4*)&As[kk][ty * 4];
            float4 rb = *(const float4*)&Bs[kk][tx * 4];
            acc[0][0] += ra.x * rb.x; acc[0][1] += ra.x * rb.y;
            acc[0][2] += ra.x * rb.z; acc[0][3] += ra.x * rb.w;
            acc[1][0] += ra.y * rb.x; acc[1][1] += ra.y * rb.y;
            acc[1][2] += ra.y * rb.z; acc[1][3] += ra.y * rb.w;
            acc[2][0] += ra.z * rb.x; acc[2][1] += ra.z * rb.y;
            acc[2][2] += ra.z * rb.z; acc[2][3] += ra.z * rb.w;
            acc[3][0] += ra.w * rb.x; acc[3][1] += ra.w * rb.y;
            acc[3][2] += ra.w * rb.z; acc[3][3] += ra.w * rb.w;
        }
        __syncthreads();
    }
#pragma unroll
    for (int i = 0; i < 4; i++) {
        int rr = row0 + ty * 4 + i;
        *(float4*)&C[(size_t)rr * ldc + col0 + tx * 4] =
            make_float4(acc[i][0], acc[i][1], acc[i][2], acc[i][3]);
    }
}

// ---------------------------------------------------------------------------
// Mega-prep: all transposes (fp32 -> fp16) + both bias fusions, one launch.
// ---------------------------------------------------------------------------
__device__ __forceinline__ void transpose_tile_h(const float* __restrict__ in, int C_in,
                                                 __half* __restrict__ out, int ld_out,
                                                 int row_off, int b)
{
    __shared__ float t[32][33];
    const int tx = threadIdx.x & 31, ty = threadIdx.x >> 5;
    const int tilesX = C_in >> 5;
    const int bx = (b % tilesX) * 32;
    const int by = (b / tilesX) * 32;
#pragma unroll
    for (int i = 0; i < 32; i += 8)
        t[ty + i][tx] = in[(size_t)(by + ty + i) * C_in + bx + tx];
    __syncthreads();
#pragma unroll
    for (int i = 0; i < 32; i += 8)
        out[(size_t)(row_off + bx + ty + i) * ld_out + by + tx] =
            __float2half(t[tx][ty + i]);
}

__global__ void prep_all_kernel(const float* __restrict__ Wfa,
                                const float* __restrict__ Wcc,
                                const float* __restrict__ Wr3,
                                const float* __restrict__ Wr2,
                                const float* __restrict__ Wl3,
                                const float* __restrict__ W3,
                                const float* __restrict__ b1,
                                const float* __restrict__ Wl1,
                                const float* __restrict__ Wl2,
                                const float* __restrict__ b2,
                                const float* __restrict__ Wr1,
                                const float* __restrict__ bl1,
                                const float* __restrict__ bl3,
                                __half* __restrict__ Wfah,
                                __half* __restrict__ Wcch,
                                __half* __restrict__ Wr2h,
                                __half* __restrict__ Wl3h,
                                __half* __restrict__ W3h,
                                float* __restrict__ bfa,
                                float* __restrict__ bcc)
{
    const int b = blockIdx.x;
    if (b < 384) {                       // Wfa [768][512] -> Wfah [512][768]
        transpose_tile_h(Wfa, 512, Wfah, F_IN, 0, b);
    } else if (b < 576) {                // Wcc [768][256] -> Wcch rows 0-255
        transpose_tile_h(Wcc, 256, Wcch, F_IN, 0, b - 384);
    } else if (b < 768) {                // Wr3 [768][256] -> Wcch rows 256-511
        transpose_tile_h(Wr3, 256, Wcch, F_IN, 256, b - 576);
    } else if (b < 832) {                // Wr2 [256][256]
        transpose_tile_h(Wr2, 256, Wr2h, HID, 0, b - 768);
    } else if (b < 896) {                // Wl3 [256][256]
        transpose_tile_h(Wl3, 256, Wl3h, HID, 0, b - 832);
    } else if (b < 928) {                // W3 [256][128] -> W3h [128][256]
        transpose_tile_h(W3, 128, W3h, HID, 0, b - 896);
    } else if (b == 928) {               // bfa = b1 @ [Wl1 | Wl2]
        int j = threadIdx.x;
        float s1 = 0.f, s2 = 0.f;
        for (int k = 0; k < PROJ; k++) {
            float b1k = b1[k];
            s1 += b1k * Wl1[(size_t)k * HID + j];
            s2 += b1k * Wl2[(size_t)k * HID + j];
        }
        bfa[j] = s1;
        bfa[256 + j] = s2;
    } else {                             // bcc = [b2 @ Wr1 + bl1 | bl3]
        int j = threadIdx.x;
        float s3 = 0.f;
        for (int k = 0; k < PROJ; k++) s3 += b2[k] * Wr1[(size_t)k * HID + j];
        bcc[j] = s3 + bl1[j];
        bcc[256 + j] = bl3[j];
    }
}

// ---------------------------------------------------------------------------
// Convert inputs fp32 -> fp16 AND zero histograms, one launch.
// ---------------------------------------------------------------------------
#define CONV_BLKS 37500   // 50000*768/4/256
#define ZERO_BLKS (((3 * N_NODES) + 1023) / 1024)

__global__ void convert_zero_kernel(const float* __restrict__ ax,
                                    const float* __restrict__ cx,
                                    __half* __restrict__ axh,
                                    __half* __restrict__ cxh,
                                    int* __restrict__ cnt)
{
    const int b = blockIdx.x;
    if (b < 2 * CONV_BLKS) {
        const float* src = (b < CONV_BLKS) ? ax : cx;
        __half* dst = (b < CONV_BLKS) ? axh : cxh;
        int i = (b % CONV_BLKS) * 256 + threadIdx.x;   // float4 index
        float4 v = ((const float4*)src)[i];
        __half2 h0 = __floats2half2_rn(v.x, v.y);
        __half2 h1 = __floats2half2_rn(v.z, v.w);
        uint2 o;
        o.x = *(uint32_t*)&h0;
        o.y = *(uint32_t*)&h1;
        ((uint2*)dst)[i] = o;
    } else {
        int i = (b - 2 * CONV_BLKS) * 1024 + threadIdx.x * 4;
        if (i < 3 * N_NODES) {
            cnt[i] = 0;
            if (i + 1 < 3 * N_NODES) cnt[i + 1] = 0;
            if (i + 2 < 3 * N_NODES) cnt[i + 2] = 0;
            if (i + 3 < 3 * N_NODES) cnt[i + 3] = 0;
        }
    }
}

// ---------------------------------------------------------------------------
// CSR build: merged across the 3 edge sets
// ---------------------------------------------------------------------------
__global__ void hist_all_kernel(const int* __restrict__ d0, int E0,
                                const int* __restrict__ d1, int E1,
                                const int* __restrict__ d2, int E2,
                                int* __restrict__ cnt)
{
    const int z = blockIdx.z;
    const int e = blockIdx.x * blockDim.x + threadIdx.x;
    const int E = (z == 0) ? E0 : (z == 1) ? E1 : E2;
    if (e >= E) return;
    const int* dst = (z == 0) ? d0 : (z == 1) ? d1 : d2;
    atomicAdd(&cnt[z * N_NODES + dst[e]], 1);
}

__global__ void exscan_all_kernel(int* __restrict__ cnt,
                                  int* __restrict__ r0,
                                  int* __restrict__ r1,
                                  int* __restrict__ r2)
{
    __shared__ int wsum[32];
    __shared__ int carry;
    const int z = blockIdx.x;
    int* cz = cnt + z * N_NODES;
    int* rowptr = (z == 0) ? r0 : (z == 1) ? r1 : r2;
    int tid = threadIdx.x, lane = tid & 31, warp = tid >> 5;
    if (tid == 0) carry = 0;
    __syncthreads();
    for (int base = 0; base < N_NODES; base += 1024) {
        int idx = base + tid;
        int v = (idx < N_NODES) ? cz[idx] : 0;
        int s = v;
#pragma unroll
        for (int off = 1; off < 32; off <<= 1) {
            int t = __shfl_up_sync(0xffffffffu, s, off);
            if (lane >= off) s += t;
        }
        if (lane == 31) wsum[warp] = s;
        __syncthreads();
        if (warp == 0) {
            int w = wsum[lane];
#pragma unroll
            for (int off = 1; off < 32; off <<= 1) {
                int t = __shfl_up_sync(0xffffffffu, w, off);
                if (lane >= off) w += t;
            }
            wsum[lane] = w;
        }
        __syncthreads();
        int woff = warp ? wsum[warp - 1] : 0;
        int myc = carry;
        int total = wsum[31];
        if (idx < N_NODES) {
            int ex = myc + woff + s - v;
            rowptr[idx] = ex;
            cz[idx] = ex;            // fill cursor
        }
        __syncthreads();
        if (tid == 0) carry = myc + total;
        __syncthreads();
    }
    if (tid == 0) rowptr[N_NODES] = carry;
}

__global__ void fill_all_kernel(const int* __restrict__ e0, int E0,
                                const int* __restrict__ e1, int E1,
                                const int* __restrict__ e2, int E2,
                                int* __restrict__ cnt,
                                int* __restrict__ c0,
                                int* __restrict__ c1,
                                int* __restrict__ c2)
{
    const int z = blockIdx.z;
    const int e = blockIdx.x * blockDim.x + threadIdx.x;
    const int E = (z == 0) ? E0 : (z == 1) ? E1 : E2;
    if (e >= E) return;
    const int* edges = (z == 0) ? e0 : (z == 1) ? e1 : e2;
    int* col = (z == 0) ? c0 : (z == 1) ? c1 : c2;
    int src = edges[e];
    int dst = edges[E + e];
    int p = atomicAdd(&cnt[z * N_NODES + dst], 1);
    col[p] = src;
}

// ---------------------------------------------------------------------------
// fp16 CSR mean aggregation: 4 nodes/block, 64 threads/node, 4 fp16 (uint2)
// per thread. fp32 accumulation inside.
// ---------------------------------------------------------------------------
__device__ __forceinline__ void csr_mean_body(const int* __restrict__ rowptr,
                                              const int* __restrict__ col,
                                              const __half* __restrict__ feat,
                                              const __half* __restrict__ add,
                                              __half* __restrict__ out, int relu)
{
    const int sub  = threadIdx.x >> 6;
    const int j    = threadIdx.x & 63;          // uint2 (4 fp16) index; row = 64 uint2
    const int node = blockIdx.x * 4 + sub;
    if (node >= N_NODES) return;

    const uint2* f2 = (const uint2*)feat;
    int s = rowptr[node], e = rowptr[node + 1];

    float4 acc = make_float4(0.f, 0.f, 0.f, 0.f);
    for (int k = s; k < e; k++) {
        uint2 v = f2[(size_t)col[k] * 64 + j];
        float2 p0 = __half22float2(*(__half2*)&v.x);
        float2 p1 = __half22float2(*(__half2*)&v.y);
        acc.x += p0.x; acc.y += p0.y; acc.z += p1.x; acc.w += p1.y;
    }
    float inv = 1.f / fmaxf((float)(e - s), 1.f);
    acc.x *= inv; acc.y *= inv; acc.z *= inv; acc.w *= inv;
    if (add) {
        uint2 a = ((const uint2*)add)[(size_t)node * 64 + j];
        float2 a0 = __half22float2(*(__half2*)&a.x);
        float2 a1 = __half22float2(*(__half2*)&a.y);
        acc.x += a0.x; acc.y += a0.y; acc.z += a1.x; acc.w += a1.y;
    }
    if (relu) {
        acc.x = fmaxf(acc.x, 0.f); acc.y = fmaxf(acc.y, 0.f);
        acc.z = fmaxf(acc.z, 0.f); acc.w = fmaxf(acc.w, 0.f);
    }
    __half2 o0 = __floats2half2_rn(acc.x, acc.y);
    __half2 o1 = __floats2half2_rn(acc.z, acc.w);
    uint2 o;
    o.x = *(uint32_t*)&o0;
    o.y = *(uint32_t*)&o1;
    ((uint2*)out)[(size_t)node * 64 + j] = o;
}

__global__ __launch_bounds__(256)
void csr_mean_kernel(const int* __restrict__ rowptr, const int* __restrict__ col,
                     const __half* __restrict__ feat,
                     const __half* __restrict__ add,
                     __half* __restrict__ out, int relu)
{
    csr_mean_body(rowptr, col, feat, add, out, relu);
}

__global__ __launch_bounds__(256)
void csr_mean2_kernel(const int* __restrict__ rp0, const int* __restrict__ col0,
                      const __half* __restrict__ A1, const __half* __restrict__ C1,
                      __half* __restrict__ h1,
                      const int* __restrict__ rp1, const int* __restrict__ col1,
                      const __half* __restrict__ A2, __half* __restrict__ M2)
{
    if (blockIdx.y == 0)
        csr_mean_body(rp0, col0, A1, C1, h1, 1);
    else
        csr_mean_body(rp1, col1, A2, nullptr, M2, 0);
}

// ---------------------------------------------------------------------------
// Host orchestration
// ---------------------------------------------------------------------------
static void launch_f16(const __half* A, int lda, const __half* Bt, int ldb,
                       void* C, int ldc, const float* bias,
                       const __half* D, int ldd, int M, int N, int K,
                       int relu, int outh)
{
    dim3 grid(N / 128, (M + 127) / 128);
    f16_gemm_kernel<<<grid, 128, SMEMH>>>(A, lda, Bt, ldb, C, ldc,
                                          bias, D, ldd, M, K, relu, outh);
}

extern "C" void kernel_launch(void* const* d_in, const int* in_sizes, int n_in,
                              void* d_out, int out_size)
{
    const float* article_x   = (const float*)d_in[0];
    const float* community_x = (const float*)d_in[1];
    const int* e_wb  = (const int*)d_in[2];
    const int* e_mb  = (const int*)d_in[3];
    const int* e_int = (const int*)d_in[4];
    const float* W1 = (const float*)d_in[5];
    const float* b1 = (const float*)d_in[6];
    const float* W2 = (const float*)d_in[7];
    const float* b2 = (const float*)d_in[8];
    const float* Wl1 = (const float*)d_in[9];
    const float* bl1 = (const float*)d_in[10];
    const float* Wr1 = (const float*)d_in[11];
    const float* Wl2 = (const float*)d_in[12];
    const float* bl2 = (const float*)d_in[13];
    const float* Wr2 = (const float*)d_in[14];
    const float* Wl3 = (const float*)d_in[15];
    const float* bl3 = (const float*)d_in[16];
    const float* Wr3 = (const float*)d_in[17];
    const float* W3  = (const float*)d_in[18];
    const float* b3  = (const float*)d_in[19];

    const int E_wb  = in_sizes[2] / 2;
    const int E_mb  = in_sizes[3] / 2;
    const int E_int = in_sizes[4] / 2;

    cudaFuncSetAttribute(f16_gemm_dual_kernel,
                         cudaFuncAttributeMaxDynamicSharedMemorySize, SMEMH);
    cudaFuncSetAttribute(f16_gemm_kernel,
                         cudaFuncAttributeMaxDynamicSharedMemorySize, SMEMH);

    __half *axh, *cxh, *A1, *A2, *C1, *CR3, *h1, *M2, *h2, *g2, *h3;
    __half *Wfah, *Wcch, *Wr2h, *Wl3h, *W3h;
    float *Wfa, *Wcc, *bfa, *bcc;
    int *rp0, *rp1, *rp2, *cnt, *col0, *col1, *col2;
    cudaGetSymbolAddress((void**)&axh, g_axh);
    cudaGetSymbolAddress((void**)&cxh, g_cxh);
    cudaGetSymbolAddress((void**)&A1, g_A1);
    cudaGetSymbolAddress((void**)&A2, g_A2);
    cudaGetSymbolAddress((void**)&C1, g_C1);
    cudaGetSymbolAddress((void**)&CR3, g_CR3);
    cudaGetSymbolAddress((void**)&h1, g_h1);
    cudaGetSymbolAddress((void**)&M2, g_M2);
    cudaGetSymbolAddress((void**)&h2, g_h2);
    cudaGetSymbolAddress((void**)&g2, g_g2);
    cudaGetSymbolAddress((void**)&h3, g_h3);
    cudaGetSymbolAddress((void**)&Wfa, g_Wfa);
    cudaGetSymbolAddress((void**)&Wcc, g_Wcc);
    cudaGetSymbolAddress((void**)&Wfah, g_Wfah);
    cudaGetSymbolAddress((void**)&Wcch, g_Wcch);
    cudaGetSymbolAddress((void**)&Wr2h, g_Wr2h);
    cudaGetSymbolAddress((void**)&Wl3h, g_Wl3h);
    cudaGetSymbolAddress((void**)&W3h, g_W3h);
    cudaGetSymbolAddress((void**)&bfa, g_bfa);
    cudaGetSymbolAddress((void**)&bcc, g_bcc);
    cudaGetSymbolAddress((void**)&rp0, g_rp0);
    cudaGetSymbolAddress((void**)&rp1, g_rp1);
    cudaGetSymbolAddress((void**)&rp2, g_rp2);
    cudaGetSymbolAddress((void**)&cnt, g_cnt);
    cudaGetSymbolAddress((void**)&col0, g_col0);
    cudaGetSymbolAddress((void**)&col1, g_col1);
    cudaGetSymbolAddress((void**)&col2, g_col2);

    const int HALVES = (N_NODES + 127) / 128;      // 391
    const int EB = (MAXE + 255) / 256;
    const int CMB = (N_NODES + 3) / 4;

    // [1] all weight folds (exact fp32)
    fold_all_kernel<<<dim3(4, 12, 3), 256>>>(W1, Wl1, Wl2, W2, Wr1, Wfa, Wcc);
    // [2] all transposes (-> fp16) + bias fusions
    prep_all_kernel<<<930, 256>>>(Wfa, Wcc, Wr3, Wr2, Wl3, W3,
                                  b1, Wl1, Wl2, b2, Wr1, bl1, bl3,
                                  Wfah, Wcch, Wr2h, Wl3h, W3h, bfa, bcc);
    // [3] convert inputs to fp16 + zero histograms
    convert_zero_kernel<<<2 * CONV_BLKS + ZERO_BLKS, 256>>>(
        article_x, community_x, axh, cxh, cnt);

    // [4] merged big GEMM (fp16): [A1|A2] and [C1|CR3]
    f16_gemm_dual_kernel<<<dim3(4, 2 * HALVES), 128, SMEMH>>>(
        axh, cxh, Wfah, Wcch, bfa, bcc, A1, A2, C1, CR3, HALVES, N_NODES);

    // [5..7] CSR builds (merged)
    hist_all_kernel<<<dim3(EB, 1, 3), 256>>>(e_wb + E_wb, E_wb,
                                             e_mb + E_mb, E_mb,
                                             e_int + E_int, E_int, cnt);
    exscan_all_kernel<<<3, 1024>>>(cnt, rp0, rp1, rp2);
    fill_all_kernel<<<dim3(EB, 1, 3), 256>>>(e_wb, E_wb, e_mb, E_mb,
                                             e_int, E_int, cnt,
                                             col0, col1, col2);

    // [8] conv1 + conv2-mean: h1 = relu(mean_wb(A1)+C1); M2 = mean_mb(A2)
    csr_mean2_kernel<<<dim3(CMB, 2), 256>>>(rp0, col0, A1, C1, h1,
                                            rp1, col1, A2, M2);
    // [9] conv2: h2 = relu(h1 @ Wr2 + bl2 + M2)   (fp16 out)
    launch_f16(h1, HID, Wr2h, HID, h2, HID, bl2, M2, HID, N_NODES, 256, HID, 1, 1);
    // [10] conv3 pre: g2 = h2 @ Wl3               (fp16 out)
    launch_f16(h2, HID, Wl3h, HID, g2, HID, nullptr, nullptr, 0, N_NODES, 256, HID, 0, 1);
    // [11] conv3: h3 = relu(mean_int(g2) + CR3)
    csr_mean_kernel<<<CMB, 256>>>(rp2, col2, g2, CR3, h3, 1);
    // [12] out = h3 @ W3 + b3                     (fp32 out)
    launch_f16(h3, HID, W3h, HID, d_out, OUT_D, b3, nullptr, 0, N_NODES, 128, HID, 0, 0);
}